// round 5
// baseline (speedup 1.0000x reference)
#include <cuda_runtime.h>
#include <cstdint>

#define BB 8
#define SS 2048
#define DD 512
#define CC 1024
#define NROW (BB*SS)          // 16384

// ---------------------------------------------------------------------------
// Scratch (device globals)
// ---------------------------------------------------------------------------
__device__ int8_t g_Xq1[(size_t)NROW*DD], g_Xq2[(size_t)NROW*DD];
__device__ int8_t g_Yq1[(size_t)NROW*DD], g_Yq2[(size_t)NROW*DD];
__device__ float  g_sX[NROW], g_sY[NROW];
__device__ int8_t g_Wxq1[DD*DD], g_Wxq2[DD*DD];
__device__ int8_t g_Wyq1[DD*DD], g_Wyq2[DD*DD];
__device__ float  g_sWx[DD], g_sWy[DD];
__device__ int8_t g_WkL1[DD*DD], g_WkL2[DD*DD], g_WkR1[DD*DD], g_WkR2[DD*DD];
__device__ int8_t g_WvL1[DD*DD], g_WvL2[DD*DD], g_WvR1[DD*DD], g_WvR2[DD*DD];
__device__ float  g_sWkL[DD], g_sWkR[DD], g_sWvL[DD], g_sWvR[DD];
__device__ float  g_Q1f[(size_t)NROW*DD], g_Q2f[(size_t)NROW*DD];
__device__ float  g_Kff[(size_t)NROW*DD];
__device__ float  g_Vtf[(size_t)BB*DD*SS];
__device__ int8_t g_Q1q1[(size_t)NROW*DD], g_Q1q2[(size_t)NROW*DD];
__device__ int8_t g_Q2q1[(size_t)NROW*DD], g_Q2q2[(size_t)NROW*DD];
__device__ int8_t g_Kfq1[(size_t)NROW*DD], g_Kfq2[(size_t)NROW*DD];
__device__ float  g_sQ1[NROW], g_sQ2[NROW], g_sKf[NROW];
__device__ int8_t g_Vtq1[(size_t)BB*DD*SS], g_Vtq2[(size_t)BB*DD*SS];
__device__ float  g_sVt[BB*DD];
__device__ float  g_P[(size_t)BB*SS*SS];
__device__ int8_t g_Pq1[(size_t)BB*SS*SS], g_Pq2[(size_t)BB*SS*SS];
__device__ float  g_sP[NROW];

// ---------------------------------------------------------------------------
// Helpers
// ---------------------------------------------------------------------------
__device__ __forceinline__ uint32_t smem_u32(const void* p) {
    uint32_t a;
    asm("{ .reg .u64 t; cvta.to.shared.u64 t, %1; cvt.u32.u64 %0, t; }"
        : "=r"(a) : "l"(p));
    return a;
}
__device__ __forceinline__ void cp16(uint32_t s, const void* g) {
    asm volatile("cp.async.cg.shared.global [%0], [%1], 16;" :: "r"(s), "l"(g));
}
#define CP_COMMIT() asm volatile("cp.async.commit_group;" ::: "memory")
#define CP_WAIT2()  asm volatile("cp.async.wait_group 2;" ::: "memory")

__device__ __forceinline__ void ldm_x4(uint32_t* r, uint32_t a) {
    asm volatile("ldmatrix.sync.aligned.m8n8.x4.shared.b16 {%0,%1,%2,%3}, [%4];"
        : "=r"(r[0]), "=r"(r[1]), "=r"(r[2]), "=r"(r[3]) : "r"(a));
}
__device__ __forceinline__ void ldm_x2(uint32_t* r, uint32_t a) {
    asm volatile("ldmatrix.sync.aligned.m8n8.x2.shared.b16 {%0,%1}, [%2];"
        : "=r"(r[0]), "=r"(r[1]) : "r"(a));
}
__device__ __forceinline__ void imma(int* d, const uint32_t* a, const uint32_t* b) {
    asm volatile(
        "mma.sync.aligned.m16n8k32.row.col.s32.s8.s8.s32 "
        "{%0,%1,%2,%3}, {%4,%5,%6,%7}, {%8,%9}, {%0,%1,%2,%3};"
        : "+r"(d[0]), "+r"(d[1]), "+r"(d[2]), "+r"(d[3])
        : "r"(a[0]), "r"(a[1]), "r"(a[2]), "r"(a[3]), "r"(b[0]), "r"(b[1]));
}

// ---------------------------------------------------------------------------
// SMEM: STAGES x 4 tiles (A1,A2,B1,B2); tile = 128 rows x 64 int8, pad to 80B.
// 80B row stride -> conflict-free ldmatrix (20 words mod 32 spreads 8 rows).
// ---------------------------------------------------------------------------
#define STAGES      4
#define ROWPB       80
#define TILE_BYTES  (128 * ROWPB)        // 10240
#define BUF_BYTES   (4 * TILE_BYTES)     // 40960
#define SMEM_TOTAL  (STAGES * BUF_BYTES) // 163840

// ---------------------------------------------------------------------------
// int8 2-term TN GEMM: C = A(MxK) @ B(NxK)^T, 128x128 CTA tile, k-chunk 64.
// v = sA[m]*sB[n]*(16384*acc_hi + 128*acc_mid)
// mode 0: Cf[m*ld+n] = alpha*v
// mode 1: Cf[m*ld+n] = v + bias[n]
// mode 2: Cf[n*ld+m] = v + bias[n]      (transposed)
// mode 3: Cf[m*ld+n] = v + add1? + add2? (+Cf if accumulate)
// mode 4: Cf[n*ld+m] += v               (transposed accumulate)
// ---------------------------------------------------------------------------
__global__ __launch_bounds__(256, 1) void imma_tn(
    const int8_t* __restrict__ A1, const int8_t* __restrict__ A2,
    const float* __restrict__ sA,
    const int8_t* __restrict__ B1, const int8_t* __restrict__ B2,
    const float* __restrict__ sB,
    int K, int lda, int ldb, long long a_bs, long long b_bs,
    int sa_bs, int sb_bs,
    int mode, float alpha, const float* __restrict__ bias,
    float* __restrict__ Cf, long long cf_bs, int cf_ld,
    const float* __restrict__ add1, const float* __restrict__ add2,
    int accumulate)
{
    extern __shared__ char smem[];
    const uint32_t sbase = smem_u32(smem);

    const int tid  = threadIdx.x;
    const int wid  = tid >> 5;
    const int lane = tid & 31;
    const int warpM = wid >> 2;      // 0..1
    const int warpN = wid & 3;       // 0..3
    const int bz = blockIdx.z;
    const int bm = blockIdx.y * 128, bn = blockIdx.x * 128;

    const int8_t* gA1 = A1 + bz * a_bs + (long long)bm * lda;
    const int8_t* gA2 = A2 + bz * a_bs + (long long)bm * lda;
    const int8_t* gB1 = B1 + bz * b_bs + (long long)bn * ldb;
    const int8_t* gB2 = B2 + bz * b_bs + (long long)bn * ldb;
    const float* sAp = sA + bz * sa_bs + bm;
    const float* sBp = sB + bz * sb_bs + bn;

    int hi[4][4][4], md[4][4][4];
#pragma unroll
    for (int i = 0; i < 4; ++i)
#pragma unroll
        for (int j = 0; j < 4; ++j)
#pragma unroll
            for (int k = 0; k < 4; ++k) { hi[i][j][k] = 0; md[i][j][k] = 0; }

    const int nch = K >> 6;   // 64-byte k chunks

    // Per-thread load geometry: tile = 512 x 16B segs; thread does segs tid, tid+256
    const int r0 = tid >> 2,        c0 = tid & 3;
    const int r1 = (tid + 256) >> 2, c1 = (tid + 256) & 3;
    const uint32_t so0 = (uint32_t)(r0 * ROWPB + c0 * 16);
    const uint32_t so1 = (uint32_t)(r1 * ROWPB + c1 * 16);

#define LOAD_CHUNK(c)                                                         \
    do {                                                                      \
        const int koff_ = (c) * 64;                                           \
        const uint32_t sb_ = sbase + ((c) % STAGES) * BUF_BYTES;              \
        const long long ga0_ = (long long)r0 * lda + koff_ + c0 * 16;         \
        const long long gb0_ = (long long)r0 * ldb + koff_ + c0 * 16;         \
        const long long ga1_ = (long long)r1 * lda + koff_ + c1 * 16;         \
        const long long gb1_ = (long long)r1 * ldb + koff_ + c1 * 16;         \
        cp16(sb_ + 0 * TILE_BYTES + so0, gA1 + ga0_);                         \
        cp16(sb_ + 1 * TILE_BYTES + so0, gA2 + ga0_);                         \
        cp16(sb_ + 2 * TILE_BYTES + so0, gB1 + gb0_);                         \
        cp16(sb_ + 3 * TILE_BYTES + so0, gB2 + gb0_);                         \
        cp16(sb_ + 0 * TILE_BYTES + so1, gA1 + ga1_);                         \
        cp16(sb_ + 1 * TILE_BYTES + so1, gA2 + ga1_);                         \
        cp16(sb_ + 2 * TILE_BYTES + so1, gB1 + gb1_);                         \
        cp16(sb_ + 3 * TILE_BYTES + so1, gB2 + gb1_);                         \
    } while (0)

#pragma unroll
    for (int s = 0; s < STAGES - 1; ++s) {
        LOAD_CHUNK(s);
        CP_COMMIT();
    }

    // ldmatrix geometry
    const int a_row = warpM * 64 + (lane & 15);
    const int a_colb = (lane >> 4) * 16;           // 0 or 16 bytes
    const int b_row = warpN * 32 + (lane & 7);
    const int b_colb = ((lane >> 3) & 1) * 16;

    for (int c = 0; c < nch; ++c) {
        CP_WAIT2();
        __syncthreads();

        const uint32_t sb = sbase + (c % STAGES) * BUF_BYTES;
        const uint32_t tA1 = sb + 0 * TILE_BYTES;
        const uint32_t tA2 = sb + 1 * TILE_BYTES;
        const uint32_t tB1 = sb + 2 * TILE_BYTES;
        const uint32_t tB2 = sb + 3 * TILE_BYTES;

#pragma unroll
        for (int ks = 0; ks < 2; ++ks) {           // two k32 steps per chunk
            uint32_t a1[4][4], a2[4][4], b1[4][2], b2[4][2];
#pragma unroll
            for (int mi = 0; mi < 4; ++mi) {
                const uint32_t off =
                    (uint32_t)((a_row + mi * 16) * ROWPB + ks * 32 + a_colb);
                ldm_x4(a1[mi], tA1 + off);
                ldm_x4(a2[mi], tA2 + off);
            }
#pragma unroll
            for (int ni = 0; ni < 4; ++ni) {
                const uint32_t off =
                    (uint32_t)((b_row + ni * 8) * ROWPB + ks * 32 + b_colb);
                ldm_x2(b1[ni], tB1 + off);
                ldm_x2(b2[ni], tB2 + off);
            }
#pragma unroll
            for (int mi = 0; mi < 4; ++mi)
#pragma unroll
                for (int ni = 0; ni < 4; ++ni) {
                    imma(hi[mi][ni], a1[mi], b1[ni]);
                    imma(md[mi][ni], a1[mi], b2[ni]);
                    imma(md[mi][ni], a2[mi], b1[ni]);
                }
        }

        if (c + STAGES - 1 < nch) LOAD_CHUNK(c + STAGES - 1);
        CP_COMMIT();
    }
#undef LOAD_CHUNK

    // ------------------------- epilogue (register direct) -------------------
    const int g = lane >> 2, tig = lane & 3;
    const long long cf_off = (long long)bz * cf_bs;

#pragma unroll
    for (int mi = 0; mi < 4; ++mi) {
        const int ml0 = warpM * 64 + mi * 16 + g;
        const float sa0 = sAp[ml0];
        const float sa1 = sAp[ml0 + 8];
#pragma unroll
        for (int ni = 0; ni < 4; ++ni) {
            const int nl = warpN * 32 + ni * 8 + tig * 2;
            const int n0 = bn + nl;
            const float sb0 = sBp[nl], sb1 = sBp[nl + 1];
            const int* h = hi[mi][ni];
            const int* m_ = md[mi][ni];
#pragma unroll
            for (int half = 0; half < 2; ++half) {
                const int m = bm + ml0 + half * 8;
                const float sa = half ? sa1 : sa0;
                float v0 = sa * sb0 * (16384.f * __int2float_rn(h[half*2+0])
                                       + 128.f * __int2float_rn(m_[half*2+0]));
                float v1 = sa * sb1 * (16384.f * __int2float_rn(h[half*2+1])
                                       + 128.f * __int2float_rn(m_[half*2+1]));
                if (mode == 0) {
                    *(float2*)&Cf[cf_off + (long long)m * cf_ld + n0] =
                        make_float2(alpha * v0, alpha * v1);
                } else if (mode == 1) {
                    v0 += __ldg(bias + n0);
                    v1 += __ldg(bias + n0 + 1);
                    *(float2*)&Cf[cf_off + (long long)m * cf_ld + n0] =
                        make_float2(v0, v1);
                } else if (mode == 2) {
                    v0 += __ldg(bias + n0);
                    v1 += __ldg(bias + n0 + 1);
                    Cf[cf_off + (long long)n0 * cf_ld + m] = v0;
                    Cf[cf_off + (long long)(n0 + 1) * cf_ld + m] = v1;
                } else if (mode == 4) {
                    const long long o0 = cf_off + (long long)n0 * cf_ld + m;
                    const long long o1 = o0 + cf_ld;
                    Cf[o0] += v0;
                    Cf[o1] += v1;
                } else {  // mode 3
                    const long long o = cf_off + (long long)m * cf_ld + n0;
                    if (add1) { float2 t = *(const float2*)&add1[o]; v0 += t.x; v1 += t.y; }
                    if (add2) { float2 t = *(const float2*)&add2[o]; v0 += t.x; v1 += t.y; }
                    if (accumulate) { float2 t = *(const float2*)&Cf[o]; v0 += t.x; v1 += t.y; }
                    *(float2*)&Cf[o] = make_float2(v0, v1);
                }
            }
        }
    }
}

// ---------------------------------------------------------------------------
// Per-row 2-term int8 quantization: x ~ s*(128*q1 + q2), s = rowmax/16000
// ---------------------------------------------------------------------------
__global__ __launch_bounds__(256) void quant_rows(
    const float* __restrict__ src, int ld, int K,
    int8_t* __restrict__ q1, int8_t* __restrict__ q2, float* __restrict__ scale)
{
    const long long row = blockIdx.x;
    const float* p = src + row * (long long)ld;
    const int t = threadIdx.x;
    __shared__ float red[8];

    float mx = 0.f;
    for (int k = t; k < K; k += 256) mx = fmaxf(mx, fabsf(p[k]));
#pragma unroll
    for (int o = 16; o > 0; o >>= 1) mx = fmaxf(mx, __shfl_xor_sync(0xffffffffu, mx, o));
    if ((t & 31) == 0) red[t >> 5] = mx;
    __syncthreads();
    mx = red[0];
#pragma unroll
    for (int w = 1; w < 8; ++w) mx = fmaxf(mx, red[w]);

    const float inv = mx > 0.f ? 16000.f / mx : 0.f;
    if (t == 0) scale[row] = mx * 6.25e-5f;  // mx/16000

    int8_t* r1 = q1 + row * (long long)K;
    int8_t* r2 = q2 + row * (long long)K;
    for (int k = t; k < K; k += 256) {
        const float tt = p[k] * inv;
        const int a = __float2int_rn(tt * 0.0078125f);
        const int b = __float2int_rn(tt - 128.f * (float)a);
        r1[k] = (int8_t)a;
        r2[k] = (int8_t)b;
    }
}

// ---------------------------------------------------------------------------
// Row softmax (rows of 2048): fp32 scores in -> quantized P out directly.
// Row max of P is 1/sum, so t = P/s = 16000 * e^(x-mx) -- no extra pass.
// ---------------------------------------------------------------------------
__global__ __launch_bounds__(256) void softmax_quant(
    const float* __restrict__ P,
    int8_t* __restrict__ Pq1, int8_t* __restrict__ Pq2,
    float* __restrict__ Pscale)
{
    const long long rb = (long long)blockIdx.x * 2048;
    const float* p = P + rb;
    const int t = threadIdx.x;
    __shared__ float red[8];

    float v[8];
    float mx = -3.0e38f;
#pragma unroll
    for (int i = 0; i < 8; ++i) {
        v[i] = p[i * 256 + t];
        mx = fmaxf(mx, v[i]);
    }
#pragma unroll
    for (int o = 16; o > 0; o >>= 1) mx = fmaxf(mx, __shfl_xor_sync(0xffffffffu, mx, o));
    if ((t & 31) == 0) red[t >> 5] = mx;
    __syncthreads();
    mx = red[0];
#pragma unroll
    for (int w = 1; w < 8; ++w) mx = fmaxf(mx, red[w]);
    __syncthreads();

    float s = 0.f;
#pragma unroll
    for (int i = 0; i < 8; ++i) {
        v[i] = __expf(v[i] - mx);
        s += v[i];
    }
#pragma unroll
    for (int o = 16; o > 0; o >>= 1) s += __shfl_xor_sync(0xffffffffu, s, o);
    if ((t & 31) == 0) red[t >> 5] = s;
    __syncthreads();
    s = red[0];
#pragma unroll
    for (int w = 1; w < 8; ++w) s += red[w];

    const float inv = 1.0f / s;
    if (t == 0) Pscale[blockIdx.x] = inv * 6.25e-5f;  // (1/s)/16000

#pragma unroll
    for (int i = 0; i < 8; ++i) {
        const float tt = 16000.f * v[i];
        const int a = __float2int_rn(tt * 0.0078125f);
        const int b = __float2int_rn(tt - 128.f * (float)a);
        Pq1[rb + i * 256 + t] = (int8_t)a;
        Pq2[rb + i * 256 + t] = (int8_t)b;
    }
}

// ---------------------------------------------------------------------------
// Launch sequence
// ---------------------------------------------------------------------------
extern "C" void kernel_launch(void* const* d_in, const int* in_sizes, int n_in,
                              void* d_out, int out_size)
{
    (void)in_sizes; (void)n_in; (void)out_size;

    const float* X    = (const float*)d_in[0];
    const float* Y    = (const float*)d_in[1];
    const float* W_xq = (const float*)d_in[2];
    const float* b_xq = (const float*)d_in[3];
    const float* W_yq = (const float*)d_in[4];
    const float* b_yq = (const float*)d_in[5];
    const float* W_fk = (const float*)d_in[6];
    const float* b_fk = (const float*)d_in[7];
    const float* W_fv = (const float*)d_in[8];
    const float* b_fv = (const float*)d_in[9];
    float* out = (float*)d_out;

#define SYM(T, name, gsym) T* name; cudaGetSymbolAddress((void**)&name, gsym)
    SYM(int8_t, Xq1, g_Xq1);  SYM(int8_t, Xq2, g_Xq2);
    SYM(int8_t, Yq1, g_Yq1);  SYM(int8_t, Yq2, g_Yq2);
    SYM(float,  sX,  g_sX);   SYM(float,  sY,  g_sY);
    SYM(int8_t, Wxq1, g_Wxq1); SYM(int8_t, Wxq2, g_Wxq2);
    SYM(int8_t, Wyq1, g_Wyq1); SYM(int8_t, Wyq2, g_Wyq2);
    SYM(float,  sWx, g_sWx);  SYM(float,  sWy, g_sWy);
    SYM(int8_t, WkL1, g_WkL1); SYM(int8_t, WkL2, g_WkL2);
    SYM(int8_t, WkR1, g_WkR1); SYM(int8_t, WkR2, g_WkR2);
    SYM(int8_t, WvL1, g_WvL1); SYM(int8_t, WvL2, g_WvL2);
    SYM(int8_t, WvR1, g_WvR1); SYM(int8_t, WvR2, g_WvR2);
    SYM(float, sWkL, g_sWkL); SYM(float, sWkR, g_sWkR);
    SYM(float, sWvL, g_sWvL); SYM(float, sWvR, g_sWvR);
    SYM(float, Q1f, g_Q1f); SYM(float, Q2f, g_Q2f);
    SYM(float, Kff, g_Kff); SYM(float, Vtf, g_Vtf);
    SYM(int8_t, Q1q1, g_Q1q1); SYM(int8_t, Q1q2, g_Q1q2);
    SYM(int8_t, Q2q1, g_Q2q1); SYM(int8_t, Q2q2, g_Q2q2);
    SYM(int8_t, Kfq1, g_Kfq1); SYM(int8_t, Kfq2, g_Kfq2);
    SYM(float, sQ1, g_sQ1); SYM(float, sQ2, g_sQ2); SYM(float, sKf, g_sKf);
    SYM(int8_t, Vtq1, g_Vtq1); SYM(int8_t, Vtq2, g_Vtq2);
    SYM(float, sVt, g_sVt);
    SYM(float, P, g_P);
    SYM(int8_t, Pq1, g_Pq1); SYM(int8_t, Pq2, g_Pq2);
    SYM(float, sP, g_sP);
#undef SYM

    cudaFuncSetAttribute(imma_tn, cudaFuncAttributeMaxDynamicSharedMemorySize, SMEM_TOTAL);

    const float scale = 0.04419417382415922f;  // 1/sqrt(512)
    const long long XBS = (long long)SS * DD;  // 2048*512
    const long long PBS = (long long)SS * SS;  // 2048*2048
    const long long VBS = (long long)DD * SS;  // 512*2048

    // ---- quantize raw inputs ----
    quant_rows<<<NROW, 256>>>(X, DD, DD, Xq1, Xq2, sX);
    quant_rows<<<NROW, 256>>>(Y, DD, DD, Yq1, Yq2, sY);
    quant_rows<<<DD, 256>>>(W_xq, DD, DD, Wxq1, Wxq2, sWx);
    quant_rows<<<DD, 256>>>(W_yq, DD, DD, Wyq1, Wyq2, sWy);
    quant_rows<<<DD, 256>>>(W_fk,      CC, DD, WkL1, WkL2, sWkL);
    quant_rows<<<DD, 256>>>(W_fk + DD, CC, DD, WkR1, WkR2, sWkR);
    quant_rows<<<DD, 256>>>(W_fv,      CC, DD, WvL1, WvL2, sWvL);
    quant_rows<<<DD, 256>>>(W_fv + DD, CC, DD, WvR1, WvR2, sWvR);

    // ---- Q projections (fp32 out) ----
    imma_tn<<<dim3(4, 16, 8), 256, SMEM_TOTAL>>>(
        Xq1, Xq2, sX, Wxq1, Wxq2, sWx, DD, DD, DD, XBS, 0, SS, 0,
        1, 1.f, b_xq, Q1f, XBS, DD, nullptr, nullptr, 0);
    imma_tn<<<dim3(4, 16, 8), 256, SMEM_TOTAL>>>(
        Yq1, Yq2, sY, Wyq1, Wyq2, sWy, DD, DD, DD, XBS, 0, SS, 0,
        1, 1.f, b_yq, Q2f, XBS, DD, nullptr, nullptr, 0);
    quant_rows<<<NROW, 256>>>(Q1f, DD, DD, Q1q1, Q1q2, sQ1);
    quant_rows<<<NROW, 256>>>(Q2f, DD, DD, Q2q1, Q2q2, sQ2);

    // ---- Kf = Q1@WfkL^T + b + Q2@WfkR^T ----
    imma_tn<<<dim3(4, 16, 8), 256, SMEM_TOTAL>>>(
        Q1q1, Q1q2, sQ1, WkL1, WkL2, sWkL, DD, DD, DD, XBS, 0, SS, 0,
        1, 1.f, b_fk, Kff, XBS, DD, nullptr, nullptr, 0);
    imma_tn<<<dim3(4, 16, 8), 256, SMEM_TOTAL>>>(
        Q2q1, Q2q2, sQ2, WkR1, WkR2, sWkR, DD, DD, DD, XBS, 0, SS, 0,
        3, 1.f, nullptr, Kff, XBS, DD, nullptr, nullptr, 1);
    quant_rows<<<NROW, 256>>>(Kff, DD, DD, Kfq1, Kfq2, sKf);

    // ---- Vt (transposed fp32) = (Q1@WfvL^T + b + Q2@WfvR^T)^T ----
    imma_tn<<<dim3(4, 16, 8), 256, SMEM_TOTAL>>>(
        Q1q1, Q1q2, sQ1, WvL1, WvL2, sWvL, DD, DD, DD, XBS, 0, SS, 0,
        2, 1.f, b_fv, Vtf, VBS, SS, nullptr, nullptr, 0);
    imma_tn<<<dim3(4, 16, 8), 256, SMEM_TOTAL>>>(
        Q2q1, Q2q2, sQ2, WvR1, WvR2, sWvR, DD, DD, DD, XBS, 0, SS, 0,
        4, 1.f, nullptr, Vtf, VBS, SS, nullptr, nullptr, 0);
    quant_rows<<<BB * DD, 256>>>(Vtf, SS, SS, Vtq1, Vtq2, sVt);

    // ---- attend(Q1): P = scale*Q1@Kf^T ; softmax-quant ; out = P@Vt^T + X + Y
    imma_tn<<<dim3(16, 16, 8), 256, SMEM_TOTAL>>>(
        Q1q1, Q1q2, sQ1, Kfq1, Kfq2, sKf, DD, DD, DD, XBS, XBS, SS, SS,
        0, scale, nullptr, P, PBS, SS, nullptr, nullptr, 0);
    softmax_quant<<<NROW, 256>>>(P, Pq1, Pq2, sP);
    imma_tn<<<dim3(4, 16, 8), 256, SMEM_TOTAL>>>(
        Pq1, Pq2, sP, Vtq1, Vtq2, sVt, SS, SS, SS, PBS, VBS, SS, DD,
        3, 1.f, nullptr, out, XBS, DD, X, Y, 0);

    // ---- attend(Q2), accumulate into out ----
    imma_tn<<<dim3(16, 16, 8), 256, SMEM_TOTAL>>>(
        Q2q1, Q2q2, sQ2, Kfq1, Kfq2, sKf, DD, DD, DD, XBS, XBS, SS, SS,
        0, scale, nullptr, P, PBS, SS, nullptr, nullptr, 0);
    softmax_quant<<<NROW, 256>>>(P, Pq1, Pq2, sP);
    imma_tn<<<dim3(4, 16, 8), 256, SMEM_TOTAL>>>(
        Pq1, Pq2, sP, Vtq1, Vtq2, sVt, SS, SS, SS, PBS, VBS, SS, DD,
        3, 1.f, nullptr, out, XBS, DD, nullptr, nullptr, 1);
}

// round 6
// speedup vs baseline: 5.1113x; 5.1113x over previous
#include <cuda_runtime.h>
#include <cuda_bf16.h>
#include <cstdint>

#define BB 8
#define SS 2048
#define DD 512
#define CC 1024
#define NROW (BB*SS)   // 16384

// ---------------------------------------------------------------------------
// Scratch (device globals), bf16 as ushort
// ---------------------------------------------------------------------------
__device__ unsigned short g_Xb[(size_t)NROW*DD], g_Yb[(size_t)NROW*DD];
__device__ unsigned short g_Wxqb[DD*DD], g_Wyqb[DD*DD];
__device__ unsigned short g_Wfkb[DD*CC], g_Wfvb[DD*CC];
__device__ unsigned short g_Qb[(size_t)NROW*CC];      // [row, 1024] = Q1|Q2
__device__ unsigned short g_Kb[(size_t)NROW*DD];
__device__ unsigned short g_Vtb[(size_t)BB*DD*SS];    // [b, d, s] transposed
__device__ float          g_P[(size_t)BB*SS*SS];
__device__ unsigned short g_Pb[(size_t)BB*SS*SS];

// ---------------------------------------------------------------------------
// Helpers
// ---------------------------------------------------------------------------
__device__ __forceinline__ uint32_t smem_u32(const void* p) {
    uint32_t a;
    asm("{ .reg .u64 t; cvta.to.shared.u64 t, %1; cvt.u32.u64 %0, t; }"
        : "=r"(a) : "l"(p));
    return a;
}
__device__ __forceinline__ void cp16(uint32_t s, const void* g) {
    asm volatile("cp.async.cg.shared.global [%0], [%1], 16;" :: "r"(s), "l"(g));
}
#define CP_COMMIT() asm volatile("cp.async.commit_group;" ::: "memory")
#define CP_WAIT2()  asm volatile("cp.async.wait_group 2;" ::: "memory")

__device__ __forceinline__ void ldm_x4(uint32_t* r, uint32_t a) {
    asm volatile("ldmatrix.sync.aligned.m8n8.x4.shared.b16 {%0,%1,%2,%3}, [%4];"
        : "=r"(r[0]), "=r"(r[1]), "=r"(r[2]), "=r"(r[3]) : "r"(a));
}
__device__ __forceinline__ void ldm_x2(uint32_t* r, uint32_t a) {
    asm volatile("ldmatrix.sync.aligned.m8n8.x2.shared.b16 {%0,%1}, [%2];"
        : "=r"(r[0]), "=r"(r[1]) : "r"(a));
}
__device__ __forceinline__ void mma_bf16(float* d, const uint32_t* a, const uint32_t* b) {
    asm volatile(
        "mma.sync.aligned.m16n8k16.row.col.f32.bf16.bf16.f32 "
        "{%0,%1,%2,%3}, {%4,%5,%6,%7}, {%8,%9}, {%0,%1,%2,%3};"
        : "+f"(d[0]), "+f"(d[1]), "+f"(d[2]), "+f"(d[3])
        : "r"(a[0]), "r"(a[1]), "r"(a[2]), "r"(a[3]), "r"(b[0]), "r"(b[1]));
}
__device__ __forceinline__ unsigned short f2b(float v) {
    return __bfloat16_as_ushort(__float2bfloat16(v));
}

// ---------------------------------------------------------------------------
// SMEM: STAGES x 2 tiles (A,B); tile = 128 rows x 64 bf16, row stride 144B
// (144B => 36-word stride; 8 ldmatrix rows hit distinct banks).
// ---------------------------------------------------------------------------
#define STAGES      4
#define ROWB        144
#define TILE_BYTES  (128 * ROWB)          // 18432
#define BUF_BYTES   (2 * TILE_BYTES)      // 36864
#define SMEM_TOTAL  (STAGES * BUF_BYTES)  // 147456

// ---------------------------------------------------------------------------
// Single-pass bf16 TN GEMM: C = A(MxK) @ B(NxK)^T, 128x128 tile, k-chunk 64.
// mode 0: Cf[m*ld+n] = alpha*acc
// mode 1: Cb[m*ld+n] = bf16(acc + bias[n])
// mode 2: Cb[n*ld+m] = bf16(acc + bias[n])   (transposed)
// mode 3: Cf[m*ld+n] = acc + add1? + add2? (+Cf if accumulate)
// ---------------------------------------------------------------------------
__global__ __launch_bounds__(256, 1) void hmma_tn(
    const unsigned short* __restrict__ A, const unsigned short* __restrict__ B,
    int K, int lda, int ldb, long long a_bs, long long b_bs,
    int mode, float alpha, const float* __restrict__ bias,
    float* __restrict__ Cf, unsigned short* __restrict__ Cb,
    long long c_bs, int c_ld,
    const float* __restrict__ add1, const float* __restrict__ add2,
    int accumulate)
{
    extern __shared__ char smem[];
    const uint32_t sbase = smem_u32(smem);

    const int tid  = threadIdx.x;
    const int wid  = tid >> 5;
    const int lane = tid & 31;
    const int warpM = wid >> 2;      // 0..1
    const int warpN = wid & 3;       // 0..3
    const int bz = blockIdx.z;
    const int bm = blockIdx.y * 128, bn = blockIdx.x * 128;

    const unsigned short* gA = A + bz * a_bs + (long long)bm * lda;
    const unsigned short* gB = B + bz * b_bs + (long long)bn * ldb;

    float acc[4][4][4];
#pragma unroll
    for (int i = 0; i < 4; ++i)
#pragma unroll
        for (int j = 0; j < 4; ++j)
#pragma unroll
            for (int k = 0; k < 4; ++k) acc[i][j][k] = 0.f;

    const int nch = K >> 6;   // k-chunks of 64

    // Load geometry: tile = 128 rows x 8 16B-segs; 1024 segs/tile, 2 tiles,
    // 256 threads -> 4 segs per thread per tile.
    const int r0 = tid >> 3, s0 = tid & 7;   // seg tid
#define LOAD_CHUNK(c)                                                        \
    do {                                                                     \
        const int koff_ = (c) * 64;                                          \
        const uint32_t sb_ = sbase + ((c) % STAGES) * BUF_BYTES;             \
        _Pragma("unroll")                                                    \
        for (int h_ = 0; h_ < 4; ++h_) {                                     \
            const int row_ = r0 + h_ * 32;                                   \
            const uint32_t so_ = (uint32_t)(row_ * ROWB + s0 * 16);          \
            const long long ge_ = (long long)row_ * lda + koff_ + s0 * 8;    \
            const long long gf_ = (long long)row_ * ldb + koff_ + s0 * 8;    \
            cp16(sb_ + so_, gA + ge_);                                       \
            cp16(sb_ + TILE_BYTES + so_, gB + gf_);                          \
        }                                                                    \
        CP_COMMIT();                                                         \
    } while (0)

#pragma unroll
    for (int s = 0; s < STAGES - 1; ++s) LOAD_CHUNK(s);

    // ldmatrix geometry
    const int a_row = warpM * 64 + (lane & 15);
    const int a_colb = (lane >> 4) * 16;            // bytes within k16 group
    const int b_row = warpN * 32 + (lane & 7);
    const int b_colb = ((lane >> 3) & 1) * 16;

    for (int c = 0; c < nch; ++c) {
        CP_WAIT2();
        __syncthreads();

        const uint32_t tA = sbase + (c % STAGES) * BUF_BYTES;
        const uint32_t tB = tA + TILE_BYTES;

#pragma unroll
        for (int ks = 0; ks < 4; ++ks) {           // four k16 steps
            uint32_t af[4][4], bf[4][2];
#pragma unroll
            for (int mi = 0; mi < 4; ++mi)
                ldm_x4(af[mi], tA + (uint32_t)((a_row + mi * 16) * ROWB
                                               + ks * 32 + a_colb));
#pragma unroll
            for (int ni = 0; ni < 4; ++ni)
                ldm_x2(bf[ni], tB + (uint32_t)((b_row + ni * 8) * ROWB
                                               + ks * 32 + b_colb));
#pragma unroll
            for (int mi = 0; mi < 4; ++mi)
#pragma unroll
                for (int ni = 0; ni < 4; ++ni)
                    mma_bf16(acc[mi][ni], af[mi], bf[ni]);
        }

        if (c + STAGES - 1 < nch) LOAD_CHUNK(c + STAGES - 1);
        else CP_COMMIT();   // keep one group per iteration for wait accounting
    }
#undef LOAD_CHUNK

    // ------------------------- epilogue (register direct) -------------------
    const int g = lane >> 2, tig = lane & 3;
    const long long c_off = (long long)bz * c_bs;

#pragma unroll
    for (int mi = 0; mi < 4; ++mi) {
#pragma unroll
        for (int ni = 0; ni < 4; ++ni) {
            const float* a = acc[mi][ni];
            const int m0 = bm + warpM * 64 + mi * 16 + g;
            const int n0 = bn + warpN * 32 + ni * 8 + tig * 2;
#pragma unroll
            for (int half = 0; half < 2; ++half) {
                const int m = m0 + half * 8;
                float v0 = a[half * 2 + 0];
                float v1 = a[half * 2 + 1];
                if (mode == 0) {
                    *(float2*)&Cf[c_off + (long long)m * c_ld + n0] =
                        make_float2(alpha * v0, alpha * v1);
                } else if (mode == 1) {
                    v0 += __ldg(bias + n0);
                    v1 += __ldg(bias + n0 + 1);
                    *(ushort2*)&Cb[c_off + (long long)m * c_ld + n0] =
                        make_ushort2(f2b(v0), f2b(v1));
                } else if (mode == 2) {
                    v0 += __ldg(bias + n0);
                    v1 += __ldg(bias + n0 + 1);
                    Cb[c_off + (long long)n0 * c_ld + m] = f2b(v0);
                    Cb[c_off + (long long)(n0 + 1) * c_ld + m] = f2b(v1);
                } else {  // mode 3
                    const long long o = c_off + (long long)m * c_ld + n0;
                    if (add1) { float2 t = *(const float2*)&add1[o]; v0 += t.x; v1 += t.y; }
                    if (add2) { float2 t = *(const float2*)&add2[o]; v0 += t.x; v1 += t.y; }
                    if (accumulate) { float2 t = *(const float2*)&Cf[o]; v0 += t.x; v1 += t.y; }
                    *(float2*)&Cf[o] = make_float2(v0, v1);
                }
            }
        }
    }
}

// ---------------------------------------------------------------------------
// fp32 -> bf16 elementwise
// ---------------------------------------------------------------------------
__global__ __launch_bounds__(256) void tobf16_kernel(
    const float* __restrict__ src, unsigned short* __restrict__ dst, int n)
{
    const int i = blockIdx.x * 256 + threadIdx.x;
    if (i < n) dst[i] = f2b(src[i]);
}

// ---------------------------------------------------------------------------
// Row softmax (rows of 2048): fp32 in -> bf16 out
// ---------------------------------------------------------------------------
__global__ __launch_bounds__(256) void softmax_bf16(
    const float* __restrict__ P, unsigned short* __restrict__ Pb)
{
    const long long rb = (long long)blockIdx.x * 2048;
    const float* p = P + rb;
    const int t = threadIdx.x;
    __shared__ float red[8];

    float v[8];
    float mx = -3.0e38f;
#pragma unroll
    for (int i = 0; i < 8; ++i) {
        v[i] = p[i * 256 + t];
        mx = fmaxf(mx, v[i]);
    }
#pragma unroll
    for (int o = 16; o > 0; o >>= 1) mx = fmaxf(mx, __shfl_xor_sync(0xffffffffu, mx, o));
    if ((t & 31) == 0) red[t >> 5] = mx;
    __syncthreads();
    mx = red[0];
#pragma unroll
    for (int w = 1; w < 8; ++w) mx = fmaxf(mx, red[w]);
    __syncthreads();

    float s = 0.f;
#pragma unroll
    for (int i = 0; i < 8; ++i) {
        v[i] = __expf(v[i] - mx);
        s += v[i];
    }
#pragma unroll
    for (int o = 16; o > 0; o >>= 1) s += __shfl_xor_sync(0xffffffffu, s, o);
    if ((t & 31) == 0) red[t >> 5] = s;
    __syncthreads();
    s = red[0];
#pragma unroll
    for (int w = 1; w < 8; ++w) s += red[w];

    const float inv = 1.0f / s;
#pragma unroll
    for (int i = 0; i < 8; ++i) Pb[rb + i * 256 + t] = f2b(v[i] * inv);
}

// ---------------------------------------------------------------------------
// Launch sequence
// ---------------------------------------------------------------------------
extern "C" void kernel_launch(void* const* d_in, const int* in_sizes, int n_in,
                              void* d_out, int out_size)
{
    (void)in_sizes; (void)n_in; (void)out_size;

    const float* X    = (const float*)d_in[0];
    const float* Y    = (const float*)d_in[1];
    const float* W_xq = (const float*)d_in[2];
    const float* b_xq = (const float*)d_in[3];
    const float* W_yq = (const float*)d_in[4];
    const float* b_yq = (const float*)d_in[5];
    const float* W_fk = (const float*)d_in[6];
    const float* b_fk = (const float*)d_in[7];
    const float* W_fv = (const float*)d_in[8];
    const float* b_fv = (const float*)d_in[9];
    float* out = (float*)d_out;

#define SYM(T, name, gsym) T* name; cudaGetSymbolAddress((void**)&name, gsym)
    SYM(unsigned short, Xb, g_Xb);   SYM(unsigned short, Yb, g_Yb);
    SYM(unsigned short, Wxqb, g_Wxqb); SYM(unsigned short, Wyqb, g_Wyqb);
    SYM(unsigned short, Wfkb, g_Wfkb); SYM(unsigned short, Wfvb, g_Wfvb);
    SYM(unsigned short, Qb, g_Qb);   SYM(unsigned short, Kb, g_Kb);
    SYM(unsigned short, Vtb, g_Vtb);
    SYM(float, P, g_P);              SYM(unsigned short, Pb, g_Pb);
#undef SYM

    cudaFuncSetAttribute(hmma_tn, cudaFuncAttributeMaxDynamicSharedMemorySize, SMEM_TOTAL);

    const float scale = 0.04419417382415922f;  // 1/sqrt(512)
    const long long XBS = (long long)SS * DD;
    const long long QBS = (long long)SS * CC;
    const long long PBS = (long long)SS * SS;
    const long long VBS = (long long)DD * SS;

    // ---- bf16 conversions ----
    const int nX = NROW * DD;
    tobf16_kernel<<<nX / 256, 256>>>(X, Xb, nX);
    tobf16_kernel<<<nX / 256, 256>>>(Y, Yb, nX);
    tobf16_kernel<<<(DD * DD) / 256, 256>>>(W_xq, Wxqb, DD * DD);
    tobf16_kernel<<<(DD * DD) / 256, 256>>>(W_yq, Wyqb, DD * DD);
    tobf16_kernel<<<(DD * CC) / 256, 256>>>(W_fk, Wfkb, DD * CC);
    tobf16_kernel<<<(DD * CC) / 256, 256>>>(W_fv, Wfvb, DD * CC);

    // ---- projections ----
    // Q1 -> Qb[:, :512]
    hmma_tn<<<dim3(4, 16, 8), 256, SMEM_TOTAL>>>(
        Xb, Wxqb, DD, DD, DD, XBS, 0,
        1, 1.f, b_xq, nullptr, Qb, QBS, CC, nullptr, nullptr, 0);
    // Q2 -> Qb[:, 512:]
    hmma_tn<<<dim3(4, 16, 8), 256, SMEM_TOTAL>>>(
        Yb, Wyqb, DD, DD, DD, XBS, 0,
        1, 1.f, b_yq, nullptr, Qb + DD, QBS, CC, nullptr, nullptr, 0);
    // Kf = Qcat @ Wfk^T + b
    hmma_tn<<<dim3(4, 16, 8), 256, SMEM_TOTAL>>>(
        Qb, Wfkb, CC, CC, CC, QBS, 0,
        1, 1.f, b_fk, nullptr, Kb, XBS, DD, nullptr, nullptr, 0);
    // Vt = (Qcat @ Wfv^T + b)^T
    hmma_tn<<<dim3(4, 16, 8), 256, SMEM_TOTAL>>>(
        Qb, Wfvb, CC, CC, CC, QBS, 0,
        2, 1.f, b_fv, nullptr, Vtb, VBS, SS, nullptr, nullptr, 0);

    // ---- attend(Q1) ----
    hmma_tn<<<dim3(16, 16, 8), 256, SMEM_TOTAL>>>(
        Qb, Kb, DD, CC, DD, QBS, XBS,
        0, scale, nullptr, P, nullptr, PBS, SS, nullptr, nullptr, 0);
    softmax_bf16<<<NROW, 256>>>(P, Pb);
    hmma_tn<<<dim3(4, 16, 8), 256, SMEM_TOTAL>>>(
        Pb, Vtb, SS, SS, SS, PBS, VBS,
        3, 1.f, nullptr, out, nullptr, XBS, DD, X, Y, 0);

    // ---- attend(Q2), accumulate ----
    hmma_tn<<<dim3(16, 16, 8), 256, SMEM_TOTAL>>>(
        Qb + DD, Kb, DD, CC, DD, QBS, XBS,
        0, scale, nullptr, P, nullptr, PBS, SS, nullptr, nullptr, 0);
    softmax_bf16<<<NROW, 256>>>(P, Pb);
    hmma_tn<<<dim3(4, 16, 8), 256, SMEM_TOTAL>>>(
        Pb, Vtb, SS, SS, SS, PBS, VBS,
        3, 1.f, nullptr, out, nullptr, XBS, DD, nullptr, nullptr, 1);
}

// round 7
// speedup vs baseline: 5.8414x; 1.1428x over previous
#include <cuda_runtime.h>
#include <cuda_bf16.h>
#include <cstdint>

#define BB 8
#define SS 2048
#define DD 512
#define CC 1024
#define NROW (BB*SS)   // 16384

// ---------------------------------------------------------------------------
// Scratch (device globals), bf16 as ushort
// ---------------------------------------------------------------------------
__device__ unsigned short g_Xb[(size_t)NROW*DD], g_Yb[(size_t)NROW*DD];
__device__ unsigned short g_Wxqb[DD*DD], g_Wyqb[DD*DD];
__device__ unsigned short g_Wfkb[DD*CC], g_Wfvb[DD*CC];
__device__ unsigned short g_Qb[(size_t)NROW*CC];      // [row, 1024] = Q1|Q2
__device__ unsigned short g_Kb[(size_t)NROW*DD];
__device__ unsigned short g_Vtb[(size_t)BB*DD*SS];    // [b, d, s]
__device__ unsigned short g_Pb[(size_t)BB*SS*SS];     // bf16 scores -> probs

// ---------------------------------------------------------------------------
// Helpers
// ---------------------------------------------------------------------------
__device__ __forceinline__ uint32_t smem_u32(const void* p) {
    uint32_t a;
    asm("{ .reg .u64 t; cvta.to.shared.u64 t, %1; cvt.u32.u64 %0, t; }"
        : "=r"(a) : "l"(p));
    return a;
}
__device__ __forceinline__ void cp16(uint32_t s, const void* g) {
    asm volatile("cp.async.cg.shared.global [%0], [%1], 16;" :: "r"(s), "l"(g));
}
#define CP_COMMIT() asm volatile("cp.async.commit_group;" ::: "memory")
#define CP_WAIT1()  asm volatile("cp.async.wait_group 1;" ::: "memory")

__device__ __forceinline__ void ldm_x4(uint32_t* r, uint32_t a) {
    asm volatile("ldmatrix.sync.aligned.m8n8.x4.shared.b16 {%0,%1,%2,%3}, [%4];"
        : "=r"(r[0]), "=r"(r[1]), "=r"(r[2]), "=r"(r[3]) : "r"(a));
}
__device__ __forceinline__ void mma_bf16(float* d, const uint32_t* a, const uint32_t* b) {
    asm volatile(
        "mma.sync.aligned.m16n8k16.row.col.f32.bf16.bf16.f32 "
        "{%0,%1,%2,%3}, {%4,%5,%6,%7}, {%8,%9}, {%0,%1,%2,%3};"
        : "+f"(d[0]), "+f"(d[1]), "+f"(d[2]), "+f"(d[3])
        : "r"(a[0]), "r"(a[1]), "r"(a[2]), "r"(a[3]), "r"(b[0]), "r"(b[1]));
}
__device__ __forceinline__ unsigned short f2b(float v) {
    return __bfloat16_as_ushort(__float2bfloat16(v));
}
__device__ __forceinline__ float b2f(unsigned short v) {
    return __bfloat162float(__ushort_as_bfloat16(v));
}

// ---------------------------------------------------------------------------
// SMEM: STAGES x (A 128x64 | B 256x64) bf16, row stride 144B (conflict-free).
// ---------------------------------------------------------------------------
#define STAGES     3
#define ROWB       144
#define A_TILE_B   (128 * ROWB)               // 18432
#define B_TILE_B   (256 * ROWB)               // 36864
#define STAGE_B    (A_TILE_B + B_TILE_B)      // 55296
#define SMEM_TOTAL (STAGES * STAGE_B)         // 165888

// ---------------------------------------------------------------------------
// Single-pass bf16 TN GEMM: C = A(MxK) @ B(NxK)^T.
// CTA tile 128(m) x 256(n), warp tile 64x64 (8 warps, 2x4), k-chunk 64.
// mode 1: Cb[m*ld+n] = bf16(acc + bias[n])
// mode 2: Cb[n*ld+m] = bf16(acc + bias[n])   (transposed)
// mode 3: Cf[m*ld+n] = acc + add1? + add2? (+Cf if accumulate)
// mode 5: Cb[m*ld+n] = bf16(alpha*acc)
// ---------------------------------------------------------------------------
__global__ __launch_bounds__(256, 1) void hmma_tn(
    const unsigned short* __restrict__ A, const unsigned short* __restrict__ B,
    int K, int lda, int ldb, long long a_bs, long long b_bs,
    int mode, float alpha, const float* __restrict__ bias,
    float* __restrict__ Cf, unsigned short* __restrict__ Cb,
    long long c_bs, int c_ld,
    const float* __restrict__ add1, const float* __restrict__ add2,
    int accumulate)
{
    extern __shared__ char smem[];
    const uint32_t sbase = smem_u32(smem);

    const int tid  = threadIdx.x;
    const int wid  = tid >> 5;
    const int lane = tid & 31;
    const int warpM = wid >> 2;      // 0..1
    const int warpN = wid & 3;       // 0..3
    const int bz = blockIdx.z;
    const int bm = blockIdx.y * 128, bn = blockIdx.x * 256;

    const unsigned short* gA = A + bz * a_bs + (long long)bm * lda;
    const unsigned short* gB = B + bz * b_bs + (long long)bn * ldb;

    float acc[4][8][4];
#pragma unroll
    for (int i = 0; i < 4; ++i)
#pragma unroll
        for (int j = 0; j < 8; ++j)
#pragma unroll
            for (int k = 0; k < 4; ++k) acc[i][j][k] = 0.f;

    const int nch = K >> 6;   // k-chunks of 64

    const int lr = tid >> 3, lc = tid & 7;   // seg geometry: 8 x 16B per row
#define LOAD_CHUNK(c)                                                        \
    do {                                                                     \
        const int koff_ = (c) * 64;                                          \
        const uint32_t sb_ = sbase + ((c) % STAGES) * STAGE_B;               \
        _Pragma("unroll")                                                    \
        for (int h_ = 0; h_ < 4; ++h_) {      /* A: 128 rows */              \
            const int row_ = lr + h_ * 32;                                   \
            cp16(sb_ + (uint32_t)(row_ * ROWB + lc * 16),                    \
                 gA + (long long)row_ * lda + koff_ + lc * 8);               \
        }                                                                    \
        _Pragma("unroll")                                                    \
        for (int h_ = 0; h_ < 8; ++h_) {      /* B: 256 rows */              \
            const int row_ = lr + h_ * 32;                                   \
            cp16(sb_ + A_TILE_B + (uint32_t)(row_ * ROWB + lc * 16),         \
                 gB + (long long)row_ * ldb + koff_ + lc * 8);               \
        }                                                                    \
        CP_COMMIT();                                                         \
    } while (0)

#pragma unroll
    for (int s = 0; s < STAGES - 1; ++s) LOAD_CHUNK(s);

    // ldmatrix geometry
    const int a_row = warpM * 64 + (lane & 15);
    const int a_colb = (lane >> 4) * 16;
    const int b_row = warpN * 64 + (lane & 7) + ((lane >> 4) & 1) * 8;
    const int b_colb = ((lane >> 3) & 1) * 16;

    for (int c = 0; c < nch; ++c) {
        CP_WAIT1();
        __syncthreads();

        const uint32_t tA = sbase + (c % STAGES) * STAGE_B;
        const uint32_t tB = tA + A_TILE_B;

#pragma unroll
        for (int ks = 0; ks < 4; ++ks) {      // four k16 steps per chunk
            uint32_t af[4][4], bfr[8][2];
#pragma unroll
            for (int mi = 0; mi < 4; ++mi)
                ldm_x4(af[mi], tA + (uint32_t)((a_row + mi * 16) * ROWB
                                               + ks * 32 + a_colb));
#pragma unroll
            for (int p = 0; p < 4; ++p) {     // n16 pair -> two n8 frags
                uint32_t r[4];
                ldm_x4(r, tB + (uint32_t)((b_row + p * 16) * ROWB
                                          + ks * 32 + b_colb));
                bfr[2*p][0] = r[0]; bfr[2*p][1] = r[1];
                bfr[2*p+1][0] = r[2]; bfr[2*p+1][1] = r[3];
            }
#pragma unroll
            for (int mi = 0; mi < 4; ++mi)
#pragma unroll
                for (int ni = 0; ni < 8; ++ni)
                    mma_bf16(acc[mi][ni], af[mi], bfr[ni]);
        }

        if (c + STAGES - 1 < nch) LOAD_CHUNK(c + STAGES - 1);
        else CP_COMMIT();   // keep one group per iteration for wait accounting
    }
#undef LOAD_CHUNK

    // ------------------------- epilogue (register direct) -------------------
    const int g = lane >> 2, tig = lane & 3;
    const long long c_off = (long long)bz * c_bs;

#pragma unroll
    for (int mi = 0; mi < 4; ++mi) {
#pragma unroll
        for (int ni = 0; ni < 8; ++ni) {
            const float* a = acc[mi][ni];
            const int m0 = bm + warpM * 64 + mi * 16 + g;
            const int n0 = bn + warpN * 64 + ni * 8 + tig * 2;
#pragma unroll
            for (int half = 0; half < 2; ++half) {
                const int m = m0 + half * 8;
                float v0 = a[half * 2 + 0];
                float v1 = a[half * 2 + 1];
                if (mode == 5) {
                    *(ushort2*)&Cb[c_off + (long long)m * c_ld + n0] =
                        make_ushort2(f2b(alpha * v0), f2b(alpha * v1));
                } else if (mode == 1) {
                    v0 += __ldg(bias + n0);
                    v1 += __ldg(bias + n0 + 1);
                    *(ushort2*)&Cb[c_off + (long long)m * c_ld + n0] =
                        make_ushort2(f2b(v0), f2b(v1));
                } else if (mode == 2) {
                    v0 += __ldg(bias + n0);
                    v1 += __ldg(bias + n0 + 1);
                    Cb[c_off + (long long)n0 * c_ld + m] = f2b(v0);
                    Cb[c_off + (long long)(n0 + 1) * c_ld + m] = f2b(v1);
                } else {  // mode 3
                    const long long o = c_off + (long long)m * c_ld + n0;
                    if (add1) { float2 t = *(const float2*)&add1[o]; v0 += t.x; v1 += t.y; }
                    if (add2) { float2 t = *(const float2*)&add2[o]; v0 += t.x; v1 += t.y; }
                    if (accumulate) { float2 t = *(const float2*)&Cf[o]; v0 += t.x; v1 += t.y; }
                    *(float2*)&Cf[o] = make_float2(v0, v1);
                }
            }
        }
    }
}

// ---------------------------------------------------------------------------
// fp32 -> bf16 elementwise
// ---------------------------------------------------------------------------
__global__ __launch_bounds__(256) void tobf16_kernel(
    const float* __restrict__ src, unsigned short* __restrict__ dst, int n)
{
    const int i = blockIdx.x * 256 + threadIdx.x;
    if (i < n) dst[i] = f2b(src[i]);
}

// ---------------------------------------------------------------------------
// Row softmax (rows of 2048): bf16 scores in -> bf16 probs out (in place)
// ---------------------------------------------------------------------------
__global__ __launch_bounds__(256) void softmax_bf16(unsigned short* __restrict__ Pb)
{
    const long long rb = (long long)blockIdx.x * 2048;
    const int t = threadIdx.x;
    __shared__ float red[8];

    float v[8];
    float mx = -3.0e38f;
#pragma unroll
    for (int i = 0; i < 8; ++i) {
        v[i] = b2f(Pb[rb + i * 256 + t]);
        mx = fmaxf(mx, v[i]);
    }
#pragma unroll
    for (int o = 16; o > 0; o >>= 1) mx = fmaxf(mx, __shfl_xor_sync(0xffffffffu, mx, o));
    if ((t & 31) == 0) red[t >> 5] = mx;
    __syncthreads();
    mx = red[0];
#pragma unroll
    for (int w = 1; w < 8; ++w) mx = fmaxf(mx, red[w]);
    __syncthreads();

    float s = 0.f;
#pragma unroll
    for (int i = 0; i < 8; ++i) {
        v[i] = __expf(v[i] - mx);
        s += v[i];
    }
#pragma unroll
    for (int o = 16; o > 0; o >>= 1) s += __shfl_xor_sync(0xffffffffu, s, o);
    if ((t & 31) == 0) red[t >> 5] = s;
    __syncthreads();
    s = red[0];
#pragma unroll
    for (int w = 1; w < 8; ++w) s += red[w];

    const float inv = 1.0f / s;
#pragma unroll
    for (int i = 0; i < 8; ++i) Pb[rb + i * 256 + t] = f2b(v[i] * inv);
}

// ---------------------------------------------------------------------------
// Launch sequence
// ---------------------------------------------------------------------------
extern "C" void kernel_launch(void* const* d_in, const int* in_sizes, int n_in,
                              void* d_out, int out_size)
{
    (void)in_sizes; (void)n_in; (void)out_size;

    const float* X    = (const float*)d_in[0];
    const float* Y    = (const float*)d_in[1];
    const float* W_xq = (const float*)d_in[2];
    const float* b_xq = (const float*)d_in[3];
    const float* W_yq = (const float*)d_in[4];
    const float* b_yq = (const float*)d_in[5];
    const float* W_fk = (const float*)d_in[6];
    const float* b_fk = (const float*)d_in[7];
    const float* W_fv = (const float*)d_in[8];
    const float* b_fv = (const float*)d_in[9];
    float* out = (float*)d_out;

#define SYM(T, name, gsym) T* name; cudaGetSymbolAddress((void**)&name, gsym)
    SYM(unsigned short, Xb, g_Xb);     SYM(unsigned short, Yb, g_Yb);
    SYM(unsigned short, Wxqb, g_Wxqb); SYM(unsigned short, Wyqb, g_Wyqb);
    SYM(unsigned short, Wfkb, g_Wfkb); SYM(unsigned short, Wfvb, g_Wfvb);
    SYM(unsigned short, Qb, g_Qb);     SYM(unsigned short, Kb, g_Kb);
    SYM(unsigned short, Vtb, g_Vtb);   SYM(unsigned short, Pb, g_Pb);
#undef SYM

    cudaFuncSetAttribute(hmma_tn, cudaFuncAttributeMaxDynamicSharedMemorySize, SMEM_TOTAL);

    const float scale = 0.04419417382415922f;  // 1/sqrt(512)
    const long long XBS = (long long)SS * DD;
    const long long QBS = (long long)SS * CC;
    const long long PBS = (long long)SS * SS;
    const long long VBS = (long long)DD * SS;

    // ---- bf16 conversions ----
    const int nX = NROW * DD;
    tobf16_kernel<<<nX / 256, 256>>>(X, Xb, nX);
    tobf16_kernel<<<nX / 256, 256>>>(Y, Yb, nX);
    tobf16_kernel<<<(DD * DD) / 256, 256>>>(W_xq, Wxqb, DD * DD);
    tobf16_kernel<<<(DD * DD) / 256, 256>>>(W_yq, Wyqb, DD * DD);
    tobf16_kernel<<<(DD * CC) / 256, 256>>>(W_fk, Wfkb, DD * CC);
    tobf16_kernel<<<(DD * CC) / 256, 256>>>(W_fv, Wfvb, DD * CC);

    // ---- projections ----
    hmma_tn<<<dim3(2, 16, 8), 256, SMEM_TOTAL>>>(          // Q1 -> Qb[:, :512]
        Xb, Wxqb, DD, DD, DD, XBS, 0,
        1, 1.f, b_xq, nullptr, Qb, QBS, CC, nullptr, nullptr, 0);
    hmma_tn<<<dim3(2, 16, 8), 256, SMEM_TOTAL>>>(          // Q2 -> Qb[:, 512:]
        Yb, Wyqb, DD, DD, DD, XBS, 0,
        1, 1.f, b_yq, nullptr, Qb + DD, QBS, CC, nullptr, nullptr, 0);
    hmma_tn<<<dim3(2, 16, 8), 256, SMEM_TOTAL>>>(          // Kf
        Qb, Wfkb, CC, CC, CC, QBS, 0,
        1, 1.f, b_fk, nullptr, Kb, XBS, DD, nullptr, nullptr, 0);
    hmma_tn<<<dim3(2, 16, 8), 256, SMEM_TOTAL>>>(          // Vt (transposed)
        Qb, Wfvb, CC, CC, CC, QBS, 0,
        2, 1.f, b_fv, nullptr, Vtb, VBS, SS, nullptr, nullptr, 0);

    // ---- attend(Q1) ----
    hmma_tn<<<dim3(8, 16, 8), 256, SMEM_TOTAL>>>(          // scores (bf16)
        Qb, Kb, DD, CC, DD, QBS, XBS,
        5, scale, nullptr, nullptr, Pb, PBS, SS, nullptr, nullptr, 0);
    softmax_bf16<<<NROW, 256>>>(Pb);
    hmma_tn<<<dim3(2, 16, 8), 256, SMEM_TOTAL>>>(          // out = P@Vt^T + X + Y
        Pb, Vtb, SS, SS, SS, PBS, VBS,
        3, 1.f, nullptr, out, nullptr, XBS, DD, X, Y, 0);

    // ---- attend(Q2), accumulate ----
    hmma_tn<<<dim3(8, 16, 8), 256, SMEM_TOTAL>>>(
        Qb + DD, Kb, DD, CC, DD, QBS, XBS,
        5, scale, nullptr, nullptr, Pb, PBS, SS, nullptr, nullptr, 0);
    softmax_bf16<<<NROW, 256>>>(Pb);
    hmma_tn<<<dim3(2, 16, 8), 256, SMEM_TOTAL>>>(
        Pb, Vtb, SS, SS, SS, PBS, VBS,
        3, 1.f, nullptr, out, nullptr, XBS, DD, nullptr, nullptr, 1);
}

// round 8
// speedup vs baseline: 6.4177x; 1.0987x over previous
#include <cuda_runtime.h>
#include <cuda_bf16.h>
#include <cstdint>

#define BB 8
#define SS 2048
#define DD 512
#define CC 1024
#define NROW (BB*SS)   // 16384

// ---------------------------------------------------------------------------
// Scratch (device globals), bf16 as ushort
// ---------------------------------------------------------------------------
__device__ unsigned short g_Xb[(size_t)NROW*DD], g_Yb[(size_t)NROW*DD];
__device__ unsigned short g_Wxqb[DD*DD], g_Wyqb[DD*DD];
__device__ unsigned short g_Wfkb[DD*CC], g_Wfvb[DD*CC];
__device__ unsigned short g_Qb[(size_t)NROW*CC];      // [row, 1024] = Q1|Q2
__device__ unsigned short g_Kb[(size_t)NROW*DD];
__device__ unsigned short g_Vtb[(size_t)BB*DD*SS];    // [b, d, s]
__device__ unsigned short g_Pb1[(size_t)BB*SS*SS];    // bf16 scores/probs (Q1)
__device__ unsigned short g_Pb2[(size_t)BB*SS*SS];    // bf16 scores/probs (Q2)

// ---------------------------------------------------------------------------
// Helpers
// ---------------------------------------------------------------------------
__device__ __forceinline__ uint32_t smem_u32(const void* p) {
    uint32_t a;
    asm("{ .reg .u64 t; cvta.to.shared.u64 t, %1; cvt.u32.u64 %0, t; }"
        : "=r"(a) : "l"(p));
    return a;
}
__device__ __forceinline__ void cp16(uint32_t s, const void* g) {
    asm volatile("cp.async.cg.shared.global [%0], [%1], 16;" :: "r"(s), "l"(g));
}
#define CP_COMMIT() asm volatile("cp.async.commit_group;" ::: "memory")
#define CP_WAIT1()  asm volatile("cp.async.wait_group 1;" ::: "memory")

__device__ __forceinline__ void ldm_x4(uint32_t* r, uint32_t a) {
    asm volatile("ldmatrix.sync.aligned.m8n8.x4.shared.b16 {%0,%1,%2,%3}, [%4];"
        : "=r"(r[0]), "=r"(r[1]), "=r"(r[2]), "=r"(r[3]) : "r"(a));
}
__device__ __forceinline__ void mma_bf16(float* d, const uint32_t* a, const uint32_t* b) {
    asm volatile(
        "mma.sync.aligned.m16n8k16.row.col.f32.bf16.bf16.f32 "
        "{%0,%1,%2,%3}, {%4,%5,%6,%7}, {%8,%9}, {%0,%1,%2,%3};"
        : "+f"(d[0]), "+f"(d[1]), "+f"(d[2]), "+f"(d[3])
        : "r"(a[0]), "r"(a[1]), "r"(a[2]), "r"(a[3]), "r"(b[0]), "r"(b[1]));
}
__device__ __forceinline__ unsigned short f2b(float v) {
    return __bfloat16_as_ushort(__float2bfloat16(v));
}
__device__ __forceinline__ float b2f(unsigned short v) {
    return __bfloat162float(__ushort_as_bfloat16(v));
}

// ---------------------------------------------------------------------------
// SMEM: STAGES x (A 128x64 | B 256x64) bf16, row stride 144B (conflict-free).
// ---------------------------------------------------------------------------
#define STAGES     3
#define ROWB       144
#define A_TILE_B   (128 * ROWB)               // 18432
#define B_TILE_B   (256 * ROWB)               // 36864
#define STAGE_B    (A_TILE_B + B_TILE_B)      // 55296
#define SMEM_TOTAL (STAGES * STAGE_B)         // 165888

// ---------------------------------------------------------------------------
// Single-pass bf16 TN GEMM, CTA tile 128x256, warp tile 64x64, k-chunk 64.
//
// z-split: if (blockIdx.z >= zsplit > 0) switch to the alt operand/output set.
// K-concat: A covers K via [Aseg1 (KA cols) | Aseg2]; B k-index wraps by bmask.
//
// mode 1: Cb[m*ld+n] = bf16(acc + bias[n])
// mode 2: Cb[n*ld+m] = bf16(acc + bias[n])   (transposed)
// mode 3: Cf[m*ld+n] = acc + add1? + add2?
// mode 5: Cb[m*ld+n] = bf16(alpha*acc)
// ---------------------------------------------------------------------------
__global__ __launch_bounds__(256, 1) void hmma_tn(
    const unsigned short* __restrict__ A, const unsigned short* __restrict__ Aseg2,
    int KA, const unsigned short* __restrict__ B, int bmask,
    int K, int lda, int ldb, long long a_bs, long long b_bs,
    int zsplit,
    int mode, float alpha, const float* __restrict__ bias,
    float* __restrict__ Cf, unsigned short* __restrict__ Cb,
    long long c_bs, int c_ld,
    const float* __restrict__ add1, const float* __restrict__ add2,
    const unsigned short* __restrict__ A_alt, const unsigned short* __restrict__ B_alt,
    const float* __restrict__ bias_alt, unsigned short* __restrict__ Cb_alt,
    long long cbs_alt, int cld_alt, int mode_alt)
{
    extern __shared__ char smem[];
    const uint32_t sbase = smem_u32(smem);

    const int tid  = threadIdx.x;
    const int wid  = tid >> 5;
    const int lane = tid & 31;
    const int warpM = wid >> 2;      // 0..1
    const int warpN = wid & 3;       // 0..3
    int bz = blockIdx.z;
    const int bm = blockIdx.y * 128, bn = blockIdx.x * 256;

    // operand-set select
    const unsigned short* Ab = A;
    const unsigned short* Bb = B;
    const float* biasp = bias;
    unsigned short* Cbp = Cb;
    long long cbs = c_bs;
    int cld = c_ld;
    int md = mode;
    if (zsplit > 0 && bz >= zsplit) {
        bz -= zsplit;
        Ab = A_alt; Bb = B_alt; biasp = bias_alt;
        Cbp = Cb_alt; cbs = cbs_alt; cld = cld_alt; md = mode_alt;
    }

    const unsigned short* gA1 = Ab + bz * a_bs + (long long)bm * lda;
    const unsigned short* gA2 =
        Aseg2 ? Aseg2 + bz * a_bs + (long long)bm * lda : nullptr;
    const unsigned short* gB = Bb + bz * b_bs + (long long)bn * ldb;

    float acc[4][8][4];
#pragma unroll
    for (int i = 0; i < 4; ++i)
#pragma unroll
        for (int j = 0; j < 8; ++j)
#pragma unroll
            for (int k = 0; k < 4; ++k) acc[i][j][k] = 0.f;

    const int nch = K >> 6;   // k-chunks of 64

    const int lr = tid >> 3, lc = tid & 7;   // seg geometry: 8 x 16B per row
#define LOAD_CHUNK(c)                                                        \
    do {                                                                     \
        const int koff_ = (c) * 64;                                          \
        const unsigned short* gAc_ = gA1; int ka_ = koff_;                   \
        if (gA2 && koff_ >= KA) { gAc_ = gA2; ka_ = koff_ - KA; }            \
        const int kb_ = koff_ & bmask;                                       \
        const uint32_t sb_ = sbase + ((c) % STAGES) * STAGE_B;               \
        _Pragma("unroll")                                                    \
        for (int h_ = 0; h_ < 4; ++h_) {      /* A: 128 rows */              \
            const int row_ = lr + h_ * 32;                                   \
            cp16(sb_ + (uint32_t)(row_ * ROWB + lc * 16),                    \
                 gAc_ + (long long)row_ * lda + ka_ + lc * 8);               \
        }                                                                    \
        _Pragma("unroll")                                                    \
        for (int h_ = 0; h_ < 8; ++h_) {      /* B: 256 rows */              \
            const int row_ = lr + h_ * 32;                                   \
            cp16(sb_ + A_TILE_B + (uint32_t)(row_ * ROWB + lc * 16),         \
                 gB + (long long)row_ * ldb + kb_ + lc * 8);                 \
        }                                                                    \
        CP_COMMIT();                                                         \
    } while (0)

#pragma unroll
    for (int s = 0; s < STAGES - 1; ++s) LOAD_CHUNK(s);

    // ldmatrix geometry
    const int a_row = warpM * 64 + (lane & 15);
    const int a_colb = (lane >> 4) * 16;
    const int b_row = warpN * 64 + (lane & 7) + ((lane >> 4) & 1) * 8;
    const int b_colb = ((lane >> 3) & 1) * 16;

    for (int c = 0; c < nch; ++c) {
        CP_WAIT1();
        __syncthreads();

        const uint32_t tA = sbase + (c % STAGES) * STAGE_B;
        const uint32_t tB = tA + A_TILE_B;

#pragma unroll
        for (int ks = 0; ks < 4; ++ks) {      // four k16 steps per chunk
            uint32_t af[4][4], bfr[8][2];
#pragma unroll
            for (int mi = 0; mi < 4; ++mi)
                ldm_x4(af[mi], tA + (uint32_t)((a_row + mi * 16) * ROWB
                                               + ks * 32 + a_colb));
#pragma unroll
            for (int p = 0; p < 4; ++p) {     // n16 pair -> two n8 frags
                uint32_t r[4];
                ldm_x4(r, tB + (uint32_t)((b_row + p * 16) * ROWB
                                          + ks * 32 + b_colb));
                bfr[2*p][0] = r[0]; bfr[2*p][1] = r[1];
                bfr[2*p+1][0] = r[2]; bfr[2*p+1][1] = r[3];
            }
#pragma unroll
            for (int mi = 0; mi < 4; ++mi)
#pragma unroll
                for (int ni = 0; ni < 8; ++ni)
                    mma_bf16(acc[mi][ni], af[mi], bfr[ni]);
        }

        if (c + STAGES - 1 < nch) LOAD_CHUNK(c + STAGES - 1);
        else CP_COMMIT();   // one group per iteration for wait accounting
    }
#undef LOAD_CHUNK

    // ------------------------- epilogue (register direct) -------------------
    const int g = lane >> 2, tig = lane & 3;
    const long long c_off = (long long)bz * cbs;

#pragma unroll
    for (int mi = 0; mi < 4; ++mi) {
#pragma unroll
        for (int ni = 0; ni < 8; ++ni) {
            const float* a = acc[mi][ni];
            const int m0 = bm + warpM * 64 + mi * 16 + g;
            const int n0 = bn + warpN * 64 + ni * 8 + tig * 2;
#pragma unroll
            for (int half = 0; half < 2; ++half) {
                const int m = m0 + half * 8;
                float v0 = a[half * 2 + 0];
                float v1 = a[half * 2 + 1];
                if (md == 5) {
                    *(ushort2*)&Cbp[c_off + (long long)m * cld + n0] =
                        make_ushort2(f2b(alpha * v0), f2b(alpha * v1));
                } else if (md == 1) {
                    v0 += __ldg(biasp + n0);
                    v1 += __ldg(biasp + n0 + 1);
                    *(ushort2*)&Cbp[c_off + (long long)m * cld + n0] =
                        make_ushort2(f2b(v0), f2b(v1));
                } else if (md == 2) {
                    v0 += __ldg(biasp + n0);
                    v1 += __ldg(biasp + n0 + 1);
                    Cbp[c_off + (long long)n0 * cld + m] = f2b(v0);
                    Cbp[c_off + (long long)(n0 + 1) * cld + m] = f2b(v1);
                } else {  // mode 3
                    const long long o = c_off + (long long)m * cld + n0;
                    if (add1) { float2 t = *(const float2*)&add1[o]; v0 += t.x; v1 += t.y; }
                    if (add2) { float2 t = *(const float2*)&add2[o]; v0 += t.x; v1 += t.y; }
                    *(float2*)&Cf[o] = make_float2(v0, v1);
                }
            }
        }
    }
}

// ---------------------------------------------------------------------------
// fp32 -> bf16: two equal-size arrays in one launch
// ---------------------------------------------------------------------------
__global__ __launch_bounds__(256) void tobf16_dual(
    const float* __restrict__ s1, unsigned short* __restrict__ d1,
    const float* __restrict__ s2, unsigned short* __restrict__ d2, int n)
{
    const int i = blockIdx.x * 256 + threadIdx.x;
    if (i < n) d1[i] = f2b(s1[i]);
    else if (i < 2 * n) d2[i - n] = f2b(s2[i - n]);
}

// ---------------------------------------------------------------------------
// Row softmax (rows of 2048) in place over two buffers in one launch
// ---------------------------------------------------------------------------
__global__ __launch_bounds__(256) void softmax_bf16(
    unsigned short* __restrict__ P1, unsigned short* __restrict__ P2)
{
    unsigned short* Pb = (blockIdx.x < NROW) ? P1 : P2;
    const long long rb = (long long)(blockIdx.x & (NROW - 1)) * 2048;
    const int t = threadIdx.x;
    __shared__ float red[8];

    float v[8];
    float mx = -3.0e38f;
#pragma unroll
    for (int i = 0; i < 8; ++i) {
        v[i] = b2f(Pb[rb + i * 256 + t]);
        mx = fmaxf(mx, v[i]);
    }
#pragma unroll
    for (int o = 16; o > 0; o >>= 1) mx = fmaxf(mx, __shfl_xor_sync(0xffffffffu, mx, o));
    if ((t & 31) == 0) red[t >> 5] = mx;
    __syncthreads();
    mx = red[0];
#pragma unroll
    for (int w = 1; w < 8; ++w) mx = fmaxf(mx, red[w]);
    __syncthreads();

    float s = 0.f;
#pragma unroll
    for (int i = 0; i < 8; ++i) {
        v[i] = __expf(v[i] - mx);
        s += v[i];
    }
#pragma unroll
    for (int o = 16; o > 0; o >>= 1) s += __shfl_xor_sync(0xffffffffu, s, o);
    if ((t & 31) == 0) red[t >> 5] = s;
    __syncthreads();
    s = red[0];
#pragma unroll
    for (int w = 1; w < 8; ++w) s += red[w];

    const float inv = 1.0f / s;
#pragma unroll
    for (int i = 0; i < 8; ++i) Pb[rb + i * 256 + t] = f2b(v[i] * inv);
}

// ---------------------------------------------------------------------------
// Launch sequence
// ---------------------------------------------------------------------------
extern "C" void kernel_launch(void* const* d_in, const int* in_sizes, int n_in,
                              void* d_out, int out_size)
{
    (void)in_sizes; (void)n_in; (void)out_size;

    const float* X    = (const float*)d_in[0];
    const float* Y    = (const float*)d_in[1];
    const float* W_xq = (const float*)d_in[2];
    const float* b_xq = (const float*)d_in[3];
    const float* W_yq = (const float*)d_in[4];
    const float* b_yq = (const float*)d_in[5];
    const float* W_fk = (const float*)d_in[6];
    const float* b_fk = (const float*)d_in[7];
    const float* W_fv = (const float*)d_in[8];
    const float* b_fv = (const float*)d_in[9];
    float* out = (float*)d_out;

#define SYM(T, name, gsym) T* name; cudaGetSymbolAddress((void**)&name, gsym)
    SYM(unsigned short, Xb, g_Xb);     SYM(unsigned short, Yb, g_Yb);
    SYM(unsigned short, Wxqb, g_Wxqb); SYM(unsigned short, Wyqb, g_Wyqb);
    SYM(unsigned short, Wfkb, g_Wfkb); SYM(unsigned short, Wfvb, g_Wfvb);
    SYM(unsigned short, Qb, g_Qb);     SYM(unsigned short, Kb, g_Kb);
    SYM(unsigned short, Vtb, g_Vtb);
    SYM(unsigned short, Pb1, g_Pb1);   SYM(unsigned short, Pb2, g_Pb2);
#undef SYM

    cudaFuncSetAttribute(hmma_tn, cudaFuncAttributeMaxDynamicSharedMemorySize, SMEM_TOTAL);

    const float scale = 0.04419417382415922f;  // 1/sqrt(512)
    const long long XBS = (long long)SS * DD;
    const long long QBS = (long long)SS * CC;
    const long long PBS = (long long)SS * SS;
    const long long VBS = (long long)DD * SS;

    // ---- bf16 conversions ----
    const int nX = NROW * DD;
    tobf16_dual<<<(2 * nX) / 256, 256>>>(X, Xb, Y, Yb, nX);
    tobf16_dual<<<(2 * DD * DD) / 256, 256>>>(W_xq, Wxqb, W_yq, Wyqb, DD * DD);
    tobf16_dual<<<(2 * DD * CC) / 256, 256>>>(W_fk, Wfkb, W_fv, Wfvb, DD * CC);

    // ---- projections: Q1 (z<8) and Q2 (z>=8) in one launch ----
    hmma_tn<<<dim3(2, 16, 16), 256, SMEM_TOTAL>>>(
        Xb, nullptr, DD, Wxqb, DD - 1,
        DD, DD, DD, XBS, 0, /*zsplit*/8,
        1, 1.f, b_xq, nullptr, Qb, QBS, CC, nullptr, nullptr,
        Yb, Wyqb, b_yq, Qb + DD, QBS, CC, 1);

    // ---- Kf (z<8, mode 1) and Vt (z>=8, mode 2 transposed) ----
    hmma_tn<<<dim3(2, 16, 16), 256, SMEM_TOTAL>>>(
        Qb, nullptr, CC, Wfkb, CC - 1,
        CC, CC, CC, QBS, 0, /*zsplit*/8,
        1, 1.f, b_fk, nullptr, Kb, XBS, DD, nullptr, nullptr,
        Qb, Wfvb, b_fv, Vtb, VBS, SS, 2);

    // ---- QK: scores for Q1 -> Pb1 (z<8) and Q2 -> Pb2 (z>=8) ----
    hmma_tn<<<dim3(8, 16, 16), 256, SMEM_TOTAL>>>(
        Qb, nullptr, DD, Kb, DD - 1,
        DD, CC, DD, QBS, XBS, /*zsplit*/8,
        5, scale, nullptr, nullptr, Pb1, PBS, SS, nullptr, nullptr,
        Qb + DD, Kb, nullptr, Pb2, PBS, SS, 5);

    // ---- softmax over both buffers ----
    softmax_bf16<<<2 * NROW, 256>>>(Pb1, Pb2);

    // ---- fused PV: out = P1@Vt^T + P2@Vt^T + X + Y  (K = 4096 concat) ----
    hmma_tn<<<dim3(2, 16, 8), 256, SMEM_TOTAL>>>(
        Pb1, Pb2, SS, Vtb, SS - 1,
        2 * SS, SS, SS, PBS, VBS, /*zsplit*/0,
        3, 1.f, nullptr, out, nullptr, XBS, DD, X, Y,
        nullptr, nullptr, nullptr, nullptr, 0, 0, 0);
}

// round 9
// speedup vs baseline: 6.7971x; 1.0591x over previous
#include <cuda_runtime.h>
#include <cuda_bf16.h>
#include <cstdint>

#define BB 8
#define SS 2048
#define DD 512
#define CC 1024
#define NROW (BB*SS)   // 16384

// ---------------------------------------------------------------------------
// Scratch (device globals), bf16 as ushort
// ---------------------------------------------------------------------------
__device__ unsigned short g_Xb[(size_t)NROW*DD], g_Yb[(size_t)NROW*DD];
__device__ unsigned short g_Wxqb[DD*DD], g_Wyqb[DD*DD];
__device__ unsigned short g_Wfkb[DD*CC], g_Wfvb[DD*CC];
__device__ unsigned short g_Qb[(size_t)NROW*CC];      // [row, 1024] = Q1|Q2
__device__ unsigned short g_Kb[(size_t)NROW*DD];
__device__ unsigned short g_Vtb[(size_t)BB*DD*SS];    // [b, d, s]
__device__ unsigned short g_Pb1[(size_t)BB*SS*SS];    // bf16 scores/probs (Q1)
__device__ unsigned short g_Pb2[(size_t)BB*SS*SS];    // bf16 scores/probs (Q2)

// ---------------------------------------------------------------------------
// Helpers
// ---------------------------------------------------------------------------
__device__ __forceinline__ uint32_t smem_u32(const void* p) {
    uint32_t a;
    asm("{ .reg .u64 t; cvta.to.shared.u64 t, %1; cvt.u32.u64 %0, t; }"
        : "=r"(a) : "l"(p));
    return a;
}
__device__ __forceinline__ void cp16(uint32_t s, const void* g) {
    asm volatile("cp.async.cg.shared.global [%0], [%1], 16;" :: "r"(s), "l"(g));
}
#define CP_COMMIT() asm volatile("cp.async.commit_group;" ::: "memory")
#define CP_WAIT1()  asm volatile("cp.async.wait_group 1;" ::: "memory")

__device__ __forceinline__ void ldm_x4(uint32_t* r, uint32_t a) {
    asm volatile("ldmatrix.sync.aligned.m8n8.x4.shared.b16 {%0,%1,%2,%3}, [%4];"
        : "=r"(r[0]), "=r"(r[1]), "=r"(r[2]), "=r"(r[3]) : "r"(a));
}
__device__ __forceinline__ void mma_bf16(float* d, const uint32_t* a, const uint32_t* b) {
    asm volatile(
        "mma.sync.aligned.m16n8k16.row.col.f32.bf16.bf16.f32 "
        "{%0,%1,%2,%3}, {%4,%5,%6,%7}, {%8,%9}, {%0,%1,%2,%3};"
        : "+f"(d[0]), "+f"(d[1]), "+f"(d[2]), "+f"(d[3])
        : "r"(a[0]), "r"(a[1]), "r"(a[2]), "r"(a[3]), "r"(b[0]), "r"(b[1]));
}
__device__ __forceinline__ unsigned short f2b(float v) {
    return __bfloat16_as_ushort(__float2bfloat16(v));
}
__device__ __forceinline__ float b2f(unsigned short v) {
    return __bfloat162float(__ushort_as_bfloat16(v));
}

// ---------------------------------------------------------------------------
// SMEM: STAGES x (A 256x64 | B 128x64) bf16, row stride 144B (conflict-free).
// ---------------------------------------------------------------------------
#define STAGES     3
#define ROWB       144
#define A_TILE_B   (256 * ROWB)               // 36864
#define B_TILE_B   (128 * ROWB)               // 18432
#define STAGE_B    (A_TILE_B + B_TILE_B)      // 55296
#define SMEM_TOTAL (STAGES * STAGE_B)         // 165888

// ---------------------------------------------------------------------------
// Single-pass bf16 TN GEMM, CTA tile 256(m) x 128(n), 512 thr (16 warps,
// warp tile 64x32 => 4 warps/SMSP for latency hiding), k-chunk 64.
//
// z-split: if (blockIdx.z >= zsplit > 0) switch to the alt operand/output set.
// K-concat: A covers K via [Aseg1 (KA cols) | Aseg2]; B k-index wraps by bmask.
//
// mode 1: Cb[m*ld+n] = bf16(acc + bias[n])
// mode 2: Cb[n*ld+m] = bf16(acc + bias[n])   (transposed)
// mode 3: Cf[m*ld+n] = acc + add1? + add2?
// mode 5: Cb[m*ld+n] = bf16(alpha*acc)
// ---------------------------------------------------------------------------
__global__ __launch_bounds__(512, 1) void hmma_tn(
    const unsigned short* __restrict__ A, const unsigned short* __restrict__ Aseg2,
    int KA, const unsigned short* __restrict__ B, int bmask,
    int K, int lda, int ldb, long long a_bs, long long b_bs,
    int zsplit,
    int mode, float alpha, const float* __restrict__ bias,
    float* __restrict__ Cf, unsigned short* __restrict__ Cb,
    long long c_bs, int c_ld,
    const float* __restrict__ add1, const float* __restrict__ add2,
    const unsigned short* __restrict__ A_alt, const unsigned short* __restrict__ B_alt,
    const float* __restrict__ bias_alt, unsigned short* __restrict__ Cb_alt,
    long long cbs_alt, int cld_alt, int mode_alt)
{
    extern __shared__ char smem[];
    const uint32_t sbase = smem_u32(smem);

    const int tid  = threadIdx.x;
    const int wid  = tid >> 5;
    const int lane = tid & 31;
    const int warpM = wid >> 2;      // 0..3 (64 rows each)
    const int warpN = wid & 3;       // 0..3 (32 cols each)
    int bz = blockIdx.z;
    const int bm = blockIdx.y * 256, bn = blockIdx.x * 128;

    // operand-set select
    const unsigned short* Ab = A;
    const unsigned short* Bb = B;
    const float* biasp = bias;
    unsigned short* Cbp = Cb;
    long long cbs = c_bs;
    int cld = c_ld;
    int md = mode;
    if (zsplit > 0 && bz >= zsplit) {
        bz -= zsplit;
        Ab = A_alt; Bb = B_alt; biasp = bias_alt;
        Cbp = Cb_alt; cbs = cbs_alt; cld = cld_alt; md = mode_alt;
    }

    const unsigned short* gA1 = Ab + bz * a_bs + (long long)bm * lda;
    const unsigned short* gA2 =
        Aseg2 ? Aseg2 + bz * a_bs + (long long)bm * lda : nullptr;
    const unsigned short* gB = Bb + bz * b_bs + (long long)bn * ldb;

    float acc[4][4][4];
#pragma unroll
    for (int i = 0; i < 4; ++i)
#pragma unroll
        for (int j = 0; j < 4; ++j)
#pragma unroll
            for (int k = 0; k < 4; ++k) acc[i][j][k] = 0.f;

    const int nch = K >> 6;   // k-chunks of 64

    const int lr = tid >> 3, lc = tid & 7;   // 64 rows x 8 segs per pass
#define LOAD_CHUNK(c)                                                        \
    do {                                                                     \
        const int koff_ = (c) * 64;                                          \
        const unsigned short* gAc_ = gA1; int ka_ = koff_;                   \
        if (gA2 && koff_ >= KA) { gAc_ = gA2; ka_ = koff_ - KA; }            \
        const int kb_ = koff_ & bmask;                                       \
        const uint32_t sb_ = sbase + ((c) % STAGES) * STAGE_B;               \
        _Pragma("unroll")                                                    \
        for (int h_ = 0; h_ < 4; ++h_) {      /* A: 256 rows */              \
            const int row_ = lr + h_ * 64;                                   \
            cp16(sb_ + (uint32_t)(row_ * ROWB + lc * 16),                    \
                 gAc_ + (long long)row_ * lda + ka_ + lc * 8);               \
        }                                                                    \
        _Pragma("unroll")                                                    \
        for (int h_ = 0; h_ < 2; ++h_) {      /* B: 128 rows */              \
            const int row_ = lr + h_ * 64;                                   \
            cp16(sb_ + A_TILE_B + (uint32_t)(row_ * ROWB + lc * 16),         \
                 gB + (long long)row_ * ldb + kb_ + lc * 8);                 \
        }                                                                    \
        CP_COMMIT();                                                         \
    } while (0)

#pragma unroll
    for (int s = 0; s < STAGES - 1; ++s) LOAD_CHUNK(s);

    // ldmatrix geometry
    const int a_row = warpM * 64 + (lane & 15);
    const int a_colb = (lane >> 4) * 16;
    const int b_row = warpN * 32 + (lane & 7) + ((lane >> 4) & 1) * 8;
    const int b_colb = ((lane >> 3) & 1) * 16;

    for (int c = 0; c < nch; ++c) {
        CP_WAIT1();
        __syncthreads();

        const uint32_t tA = sbase + (c % STAGES) * STAGE_B;
        const uint32_t tB = tA + A_TILE_B;

#pragma unroll
        for (int ks = 0; ks < 4; ++ks) {      // four k16 steps per chunk
            uint32_t af[4][4], bfr[4][2];
#pragma unroll
            for (int mi = 0; mi < 4; ++mi)
                ldm_x4(af[mi], tA + (uint32_t)((a_row + mi * 16) * ROWB
                                               + ks * 32 + a_colb));
#pragma unroll
            for (int p = 0; p < 2; ++p) {     // n16 pair -> two n8 frags
                uint32_t r[4];
                ldm_x4(r, tB + (uint32_t)((b_row + p * 16) * ROWB
                                          + ks * 32 + b_colb));
                bfr[2*p][0] = r[0]; bfr[2*p][1] = r[1];
                bfr[2*p+1][0] = r[2]; bfr[2*p+1][1] = r[3];
            }
#pragma unroll
            for (int mi = 0; mi < 4; ++mi)
#pragma unroll
                for (int ni = 0; ni < 4; ++ni)
                    mma_bf16(acc[mi][ni], af[mi], bfr[ni]);
        }

        if (c + STAGES - 1 < nch) LOAD_CHUNK(c + STAGES - 1);
        else CP_COMMIT();   // one group per iteration for wait accounting
    }
#undef LOAD_CHUNK

    // ------------------------- epilogue (register direct) -------------------
    const int g = lane >> 2, tig = lane & 3;
    const long long c_off = (long long)bz * cbs;

#pragma unroll
    for (int mi = 0; mi < 4; ++mi) {
#pragma unroll
        for (int ni = 0; ni < 4; ++ni) {
            const float* a = acc[mi][ni];
            const int m0 = bm + warpM * 64 + mi * 16 + g;
            const int n0 = bn + warpN * 32 + ni * 8 + tig * 2;
#pragma unroll
            for (int half = 0; half < 2; ++half) {
                const int m = m0 + half * 8;
                float v0 = a[half * 2 + 0];
                float v1 = a[half * 2 + 1];
                if (md == 5) {
                    *(ushort2*)&Cbp[c_off + (long long)m * cld + n0] =
                        make_ushort2(f2b(alpha * v0), f2b(alpha * v1));
                } else if (md == 1) {
                    v0 += __ldg(biasp + n0);
                    v1 += __ldg(biasp + n0 + 1);
                    *(ushort2*)&Cbp[c_off + (long long)m * cld + n0] =
                        make_ushort2(f2b(v0), f2b(v1));
                } else if (md == 2) {
                    v0 += __ldg(biasp + n0);
                    v1 += __ldg(biasp + n0 + 1);
                    Cbp[c_off + (long long)n0 * cld + m] = f2b(v0);
                    Cbp[c_off + (long long)(n0 + 1) * cld + m] = f2b(v1);
                } else {  // mode 3
                    const long long o = c_off + (long long)m * cld + n0;
                    if (add1) { float2 t = *(const float2*)&add1[o]; v0 += t.x; v1 += t.y; }
                    if (add2) { float2 t = *(const float2*)&add2[o]; v0 += t.x; v1 += t.y; }
                    *(float2*)&Cf[o] = make_float2(v0, v1);
                }
            }
        }
    }
}

// ---------------------------------------------------------------------------
// fp32 -> bf16: two equal-size arrays in one launch
// ---------------------------------------------------------------------------
__global__ __launch_bounds__(256) void tobf16_dual(
    const float* __restrict__ s1, unsigned short* __restrict__ d1,
    const float* __restrict__ s2, unsigned short* __restrict__ d2, int n)
{
    const int i = blockIdx.x * 256 + threadIdx.x;
    if (i < n) d1[i] = f2b(s1[i]);
    else if (i < 2 * n) d2[i - n] = f2b(s2[i - n]);
}

// ---------------------------------------------------------------------------
// Row softmax (rows of 2048) in place over two buffers in one launch
// ---------------------------------------------------------------------------
__global__ __launch_bounds__(256) void softmax_bf16(
    unsigned short* __restrict__ P1, unsigned short* __restrict__ P2)
{
    unsigned short* Pb = (blockIdx.x < NROW) ? P1 : P2;
    const long long rb = (long long)(blockIdx.x & (NROW - 1)) * 2048;
    const int t = threadIdx.x;
    __shared__ float red[8];

    float v[8];
    float mx = -3.0e38f;
#pragma unroll
    for (int i = 0; i < 8; ++i) {
        v[i] = b2f(Pb[rb + i * 256 + t]);
        mx = fmaxf(mx, v[i]);
    }
#pragma unroll
    for (int o = 16; o > 0; o >>= 1) mx = fmaxf(mx, __shfl_xor_sync(0xffffffffu, mx, o));
    if ((t & 31) == 0) red[t >> 5] = mx;
    __syncthreads();
    mx = red[0];
#pragma unroll
    for (int w = 1; w < 8; ++w) mx = fmaxf(mx, red[w]);
    __syncthreads();

    float s = 0.f;
#pragma unroll
    for (int i = 0; i < 8; ++i) {
        v[i] = __expf(v[i] - mx);
        s += v[i];
    }
#pragma unroll
    for (int o = 16; o > 0; o >>= 1) s += __shfl_xor_sync(0xffffffffu, s, o);
    if ((t & 31) == 0) red[t >> 5] = s;
    __syncthreads();
    s = red[0];
#pragma unroll
    for (int w = 1; w < 8; ++w) s += red[w];

    const float inv = 1.0f / s;
#pragma unroll
    for (int i = 0; i < 8; ++i) Pb[rb + i * 256 + t] = f2b(v[i] * inv);
}

// ---------------------------------------------------------------------------
// Launch sequence
// ---------------------------------------------------------------------------
extern "C" void kernel_launch(void* const* d_in, const int* in_sizes, int n_in,
                              void* d_out, int out_size)
{
    (void)in_sizes; (void)n_in; (void)out_size;

    const float* X    = (const float*)d_in[0];
    const float* Y    = (const float*)d_in[1];
    const float* W_xq = (const float*)d_in[2];
    const float* b_xq = (const float*)d_in[3];
    const float* W_yq = (const float*)d_in[4];
    const float* b_yq = (const float*)d_in[5];
    const float* W_fk = (const float*)d_in[6];
    const float* b_fk = (const float*)d_in[7];
    const float* W_fv = (const float*)d_in[8];
    const float* b_fv = (const float*)d_in[9];
    float* out = (float*)d_out;

#define SYM(T, name, gsym) T* name; cudaGetSymbolAddress((void**)&name, gsym)
    SYM(unsigned short, Xb, g_Xb);     SYM(unsigned short, Yb, g_Yb);
    SYM(unsigned short, Wxqb, g_Wxqb); SYM(unsigned short, Wyqb, g_Wyqb);
    SYM(unsigned short, Wfkb, g_Wfkb); SYM(unsigned short, Wfvb, g_Wfvb);
    SYM(unsigned short, Qb, g_Qb);     SYM(unsigned short, Kb, g_Kb);
    SYM(unsigned short, Vtb, g_Vtb);
    SYM(unsigned short, Pb1, g_Pb1);   SYM(unsigned short, Pb2, g_Pb2);
#undef SYM

    cudaFuncSetAttribute(hmma_tn, cudaFuncAttributeMaxDynamicSharedMemorySize, SMEM_TOTAL);

    const float scale = 0.04419417382415922f;  // 1/sqrt(512)
    const long long XBS = (long long)SS * DD;
    const long long QBS = (long long)SS * CC;
    const long long PBS = (long long)SS * SS;
    const long long VBS = (long long)DD * SS;

    // ---- bf16 conversions ----
    const int nX = NROW * DD;
    tobf16_dual<<<(2 * nX) / 256, 256>>>(X, Xb, Y, Yb, nX);
    tobf16_dual<<<(2 * DD * DD) / 256, 256>>>(W_xq, Wxqb, W_yq, Wyqb, DD * DD);
    tobf16_dual<<<(2 * DD * CC) / 256, 256>>>(W_fk, Wfkb, W_fv, Wfvb, DD * CC);

    // ---- projections: Q1 (z<8) and Q2 (z>=8) in one launch ----
    hmma_tn<<<dim3(4, 8, 16), 512, SMEM_TOTAL>>>(
        Xb, nullptr, DD, Wxqb, DD - 1,
        DD, DD, DD, XBS, 0, /*zsplit*/8,
        1, 1.f, b_xq, nullptr, Qb, QBS, CC, nullptr, nullptr,
        Yb, Wyqb, b_yq, Qb + DD, QBS, CC, 1);

    // ---- Kf (z<8, mode 1) and Vt (z>=8, mode 2 transposed) ----
    hmma_tn<<<dim3(4, 8, 16), 512, SMEM_TOTAL>>>(
        Qb, nullptr, CC, Wfkb, CC - 1,
        CC, CC, CC, QBS, 0, /*zsplit*/8,
        1, 1.f, b_fk, nullptr, Kb, XBS, DD, nullptr, nullptr,
        Qb, Wfvb, b_fv, Vtb, VBS, SS, 2);

    // ---- QK: scores for Q1 -> Pb1 (z<8) and Q2 -> Pb2 (z>=8) ----
    hmma_tn<<<dim3(16, 8, 16), 512, SMEM_TOTAL>>>(
        Qb, nullptr, DD, Kb, DD - 1,
        DD, CC, DD, QBS, XBS, /*zsplit*/8,
        5, scale, nullptr, nullptr, Pb1, PBS, SS, nullptr, nullptr,
        Qb + DD, Kb, nullptr, Pb2, PBS, SS, 5);

    // ---- softmax over both buffers ----
    softmax_bf16<<<2 * NROW, 256>>>(Pb1, Pb2);

    // ---- fused PV: out = P1@Vt^T + P2@Vt^T + X + Y  (K = 4096 concat) ----
    hmma_tn<<<dim3(4, 8, 8), 512, SMEM_TOTAL>>>(
        Pb1, Pb2, SS, Vtb, SS - 1,
        2 * SS, SS, SS, PBS, VBS, /*zsplit*/0,
        3, 1.f, nullptr, out, nullptr, XBS, DD, X, Y,
        nullptr, nullptr, nullptr, nullptr, 0, 0, 0);
}

// round 10
// speedup vs baseline: 6.8347x; 1.0055x over previous
#include <cuda_runtime.h>
#include <cuda_bf16.h>
#include <cstdint>

#define BB 8
#define SS 2048
#define DD 512
#define CC 1024
#define NROW (BB*SS)   // 16384

// ---------------------------------------------------------------------------
// Scratch (device globals), bf16 as ushort
// ---------------------------------------------------------------------------
__device__ unsigned short g_Xb[(size_t)NROW*DD], g_Yb[(size_t)NROW*DD];
__device__ unsigned short g_Wxqb[DD*DD], g_Wyqb[DD*DD];
__device__ unsigned short g_Wfkb[DD*CC], g_Wfvb[DD*CC];
__device__ unsigned short g_Qb[(size_t)NROW*CC];      // [row, 1024] = Q1|Q2
__device__ unsigned short g_Kb[(size_t)NROW*DD];
__device__ unsigned short g_Vtb[(size_t)BB*DD*SS];    // [b, d, s]
__device__ unsigned short g_Pb1[(size_t)BB*SS*SS];    // bf16 scores/probs (Q1)
__device__ unsigned short g_Pb2[(size_t)BB*SS*SS];    // bf16 scores/probs (Q2)

// ---------------------------------------------------------------------------
// Helpers
// ---------------------------------------------------------------------------
__device__ __forceinline__ uint32_t smem_u32(const void* p) {
    uint32_t a;
    asm("{ .reg .u64 t; cvta.to.shared.u64 t, %1; cvt.u32.u64 %0, t; }"
        : "=r"(a) : "l"(p));
    return a;
}
__device__ __forceinline__ void cp16(uint32_t s, const void* g) {
    asm volatile("cp.async.cg.shared.global [%0], [%1], 16;" :: "r"(s), "l"(g));
}
#define CP_COMMIT() asm volatile("cp.async.commit_group;" ::: "memory")
#define CP_WAIT1()  asm volatile("cp.async.wait_group 1;" ::: "memory")

__device__ __forceinline__ void ldm_x4(uint32_t* r, uint32_t a) {
    asm volatile("ldmatrix.sync.aligned.m8n8.x4.shared.b16 {%0,%1,%2,%3}, [%4];"
        : "=r"(r[0]), "=r"(r[1]), "=r"(r[2]), "=r"(r[3]) : "r"(a));
}
__device__ __forceinline__ void mma_bf16(float* d, const uint32_t* a, const uint32_t* b) {
    asm volatile(
        "mma.sync.aligned.m16n8k16.row.col.f32.bf16.bf16.f32 "
        "{%0,%1,%2,%3}, {%4,%5,%6,%7}, {%8,%9}, {%0,%1,%2,%3};"
        : "+f"(d[0]), "+f"(d[1]), "+f"(d[2]), "+f"(d[3])
        : "r"(a[0]), "r"(a[1]), "r"(a[2]), "r"(a[3]), "r"(b[0]), "r"(b[1]));
}
__device__ __forceinline__ unsigned short f2b(float v) {
    return __bfloat16_as_ushort(__float2bfloat16(v));
}
__device__ __forceinline__ float b2f(unsigned short v) {
    return __bfloat162float(__ushort_as_bfloat16(v));
}

// ---------------------------------------------------------------------------
// SMEM: STAGES x (A 128x64 | B 128x64) bf16, row stride 144B (conflict-free).
// 108KB per CTA -> two CTAs co-resident per SM.
// ---------------------------------------------------------------------------
#define STAGES     3
#define ROWB       144
#define A_TILE_B   (128 * ROWB)               // 18432
#define B_TILE_B   (128 * ROWB)               // 18432
#define STAGE_B    (A_TILE_B + B_TILE_B)      // 36864
#define SMEM_TOTAL (STAGES * STAGE_B)         // 110592

// ---------------------------------------------------------------------------
// Single-pass bf16 TN GEMM, CTA tile 128(m) x 128(n), 256 thr (8 warps,
// warp tile 64x32), k-chunk 64, 2 CTAs/SM for bubble overlap.
//
// z-split: if (blockIdx.z >= zsplit > 0) switch to the alt operand/output set.
// K-concat: A covers K via [Aseg1 (KA cols) | Aseg2]; B k-index wraps by bmask.
//
// mode 1: Cb[m*ld+n] = bf16(acc + bias[n])
// mode 2: Cb[n*ld+m] = bf16(acc + bias[n])   (transposed)
// mode 3: Cf[m*ld+n] = acc + add1? + add2?
// mode 5: Cb[m*ld+n] = bf16(alpha*acc)
// ---------------------------------------------------------------------------
__global__ __launch_bounds__(256, 2) void hmma_tn(
    const unsigned short* __restrict__ A, const unsigned short* __restrict__ Aseg2,
    int KA, const unsigned short* __restrict__ B, int bmask,
    int K, int lda, int ldb, long long a_bs, long long b_bs,
    int zsplit,
    int mode, float alpha, const float* __restrict__ bias,
    float* __restrict__ Cf, unsigned short* __restrict__ Cb,
    long long c_bs, int c_ld,
    const float* __restrict__ add1, const float* __restrict__ add2,
    const unsigned short* __restrict__ A_alt, const unsigned short* __restrict__ B_alt,
    const float* __restrict__ bias_alt, unsigned short* __restrict__ Cb_alt,
    long long cbs_alt, int cld_alt, int mode_alt)
{
    extern __shared__ char smem[];
    const uint32_t sbase = smem_u32(smem);

    const int tid  = threadIdx.x;
    const int wid  = tid >> 5;
    const int lane = tid & 31;
    const int warpM = wid >> 2;      // 0..1 (64 rows each)
    const int warpN = wid & 3;       // 0..3 (32 cols each)
    int bz = blockIdx.z;
    const int bm = blockIdx.y * 128, bn = blockIdx.x * 128;

    // operand-set select
    const unsigned short* Ab = A;
    const unsigned short* Bb = B;
    const float* biasp = bias;
    unsigned short* Cbp = Cb;
    long long cbs = c_bs;
    int cld = c_ld;
    int md = mode;
    if (zsplit > 0 && bz >= zsplit) {
        bz -= zsplit;
        Ab = A_alt; Bb = B_alt; biasp = bias_alt;
        Cbp = Cb_alt; cbs = cbs_alt; cld = cld_alt; md = mode_alt;
    }

    const unsigned short* gA1 = Ab + bz * a_bs + (long long)bm * lda;
    const unsigned short* gA2 =
        Aseg2 ? Aseg2 + bz * a_bs + (long long)bm * lda : nullptr;
    const unsigned short* gB = Bb + bz * b_bs + (long long)bn * ldb;

    float acc[4][4][4];
#pragma unroll
    for (int i = 0; i < 4; ++i)
#pragma unroll
        for (int j = 0; j < 4; ++j)
#pragma unroll
            for (int k = 0; k < 4; ++k) acc[i][j][k] = 0.f;

    const int nch = K >> 6;   // k-chunks of 64

    const int lr = tid >> 3, lc = tid & 7;   // 32 rows x 8 segs per pass
#define LOAD_CHUNK(c)                                                        \
    do {                                                                     \
        const int koff_ = (c) * 64;                                          \
        const unsigned short* gAc_ = gA1; int ka_ = koff_;                   \
        if (gA2 && koff_ >= KA) { gAc_ = gA2; ka_ = koff_ - KA; }            \
        const int kb_ = koff_ & bmask;                                       \
        const uint32_t sb_ = sbase + ((c) % STAGES) * STAGE_B;               \
        _Pragma("unroll")                                                    \
        for (int h_ = 0; h_ < 4; ++h_) {      /* A: 128 rows */              \
            const int row_ = lr + h_ * 32;                                   \
            cp16(sb_ + (uint32_t)(row_ * ROWB + lc * 16),                    \
                 gAc_ + (long long)row_ * lda + ka_ + lc * 8);               \
        }                                                                    \
        _Pragma("unroll")                                                    \
        for (int h_ = 0; h_ < 4; ++h_) {      /* B: 128 rows */              \
            const int row_ = lr + h_ * 32;                                   \
            cp16(sb_ + A_TILE_B + (uint32_t)(row_ * ROWB + lc * 16),         \
                 gB + (long long)row_ * ldb + kb_ + lc * 8);                 \
        }                                                                    \
        CP_COMMIT();                                                         \
    } while (0)

#pragma unroll
    for (int s = 0; s < STAGES - 1; ++s) LOAD_CHUNK(s);

    // ldmatrix geometry
    const int a_row = warpM * 64 + (lane & 15);
    const int a_colb = (lane >> 4) * 16;
    const int b_row = warpN * 32 + (lane & 7) + ((lane >> 4) & 1) * 8;
    const int b_colb = ((lane >> 3) & 1) * 16;

    for (int c = 0; c < nch; ++c) {
        CP_WAIT1();
        __syncthreads();

        // Issue next chunk's loads first: buffer (c+2)%3 was last read at
        // iter c-1; the barrier above ordered those reads before these writes.
        if (c + STAGES - 1 < nch) LOAD_CHUNK(c + STAGES - 1);
        else CP_COMMIT();   // one group per iteration for wait accounting

        const uint32_t tA = sbase + (c % STAGES) * STAGE_B;
        const uint32_t tB = tA + A_TILE_B;

#pragma unroll
        for (int ks = 0; ks < 4; ++ks) {      // four k16 steps per chunk
            uint32_t af[4][4], bfr[4][2];
#pragma unroll
            for (int mi = 0; mi < 4; ++mi)
                ldm_x4(af[mi], tA + (uint32_t)((a_row + mi * 16) * ROWB
                                               + ks * 32 + a_colb));
#pragma unroll
            for (int p = 0; p < 2; ++p) {     // n16 pair -> two n8 frags
                uint32_t r[4];
                ldm_x4(r, tB + (uint32_t)((b_row + p * 16) * ROWB
                                          + ks * 32 + b_colb));
                bfr[2*p][0] = r[0]; bfr[2*p][1] = r[1];
                bfr[2*p+1][0] = r[2]; bfr[2*p+1][1] = r[3];
            }
#pragma unroll
            for (int mi = 0; mi < 4; ++mi)
#pragma unroll
                for (int ni = 0; ni < 4; ++ni)
                    mma_bf16(acc[mi][ni], af[mi], bfr[ni]);
        }
    }
#undef LOAD_CHUNK

    // ------------------------- epilogue (register direct) -------------------
    const int g = lane >> 2, tig = lane & 3;
    const long long c_off = (long long)bz * cbs;

#pragma unroll
    for (int mi = 0; mi < 4; ++mi) {
#pragma unroll
        for (int ni = 0; ni < 4; ++ni) {
            const float* a = acc[mi][ni];
            const int m0 = bm + warpM * 64 + mi * 16 + g;
            const int n0 = bn + warpN * 32 + ni * 8 + tig * 2;
#pragma unroll
            for (int half = 0; half < 2; ++half) {
                const int m = m0 + half * 8;
                float v0 = a[half * 2 + 0];
                float v1 = a[half * 2 + 1];
                if (md == 5) {
                    *(ushort2*)&Cbp[c_off + (long long)m * cld + n0] =
                        make_ushort2(f2b(alpha * v0), f2b(alpha * v1));
                } else if (md == 1) {
                    v0 += __ldg(biasp + n0);
                    v1 += __ldg(biasp + n0 + 1);
                    *(ushort2*)&Cbp[c_off + (long long)m * cld + n0] =
                        make_ushort2(f2b(v0), f2b(v1));
                } else if (md == 2) {
                    v0 += __ldg(biasp + n0);
                    v1 += __ldg(biasp + n0 + 1);
                    Cbp[c_off + (long long)n0 * cld + m] = f2b(v0);
                    Cbp[c_off + (long long)(n0 + 1) * cld + m] = f2b(v1);
                } else {  // mode 3
                    const long long o = c_off + (long long)m * cld + n0;
                    if (add1) { float2 t = *(const float2*)&add1[o]; v0 += t.x; v1 += t.y; }
                    if (add2) { float2 t = *(const float2*)&add2[o]; v0 += t.x; v1 += t.y; }
                    *(float2*)&Cf[o] = make_float2(v0, v1);
                }
            }
        }
    }
}

// ---------------------------------------------------------------------------
// fp32 -> bf16: two equal-size arrays in one launch
// ---------------------------------------------------------------------------
__global__ __launch_bounds__(256) void tobf16_dual(
    const float* __restrict__ s1, unsigned short* __restrict__ d1,
    const float* __restrict__ s2, unsigned short* __restrict__ d2, int n)
{
    const int i = blockIdx.x * 256 + threadIdx.x;
    if (i < n) d1[i] = f2b(s1[i]);
    else if (i < 2 * n) d2[i - n] = f2b(s2[i - n]);
}

// ---------------------------------------------------------------------------
// Row softmax (rows of 2048) in place over two buffers in one launch
// ---------------------------------------------------------------------------
__global__ __launch_bounds__(256) void softmax_bf16(
    unsigned short* __restrict__ P1, unsigned short* __restrict__ P2)
{
    unsigned short* Pb = (blockIdx.x < NROW) ? P1 : P2;
    const long long rb = (long long)(blockIdx.x & (NROW - 1)) * 2048;
    const int t = threadIdx.x;
    __shared__ float red[8];

    float v[8];
    float mx = -3.0e38f;
#pragma unroll
    for (int i = 0; i < 8; ++i) {
        v[i] = b2f(Pb[rb + i * 256 + t]);
        mx = fmaxf(mx, v[i]);
    }
#pragma unroll
    for (int o = 16; o > 0; o >>= 1) mx = fmaxf(mx, __shfl_xor_sync(0xffffffffu, mx, o));
    if ((t & 31) == 0) red[t >> 5] = mx;
    __syncthreads();
    mx = red[0];
#pragma unroll
    for (int w = 1; w < 8; ++w) mx = fmaxf(mx, red[w]);
    __syncthreads();

    float s = 0.f;
#pragma unroll
    for (int i = 0; i < 8; ++i) {
        v[i] = __expf(v[i] - mx);
        s += v[i];
    }
#pragma unroll
    for (int o = 16; o > 0; o >>= 1) s += __shfl_xor_sync(0xffffffffu, s, o);
    if ((t & 31) == 0) red[t >> 5] = s;
    __syncthreads();
    s = red[0];
#pragma unroll
    for (int w = 1; w < 8; ++w) s += red[w];

    const float inv = 1.0f / s;
#pragma unroll
    for (int i = 0; i < 8; ++i) Pb[rb + i * 256 + t] = f2b(v[i] * inv);
}

// ---------------------------------------------------------------------------
// Launch sequence
// ---------------------------------------------------------------------------
extern "C" void kernel_launch(void* const* d_in, const int* in_sizes, int n_in,
                              void* d_out, int out_size)
{
    (void)in_sizes; (void)n_in; (void)out_size;

    const float* X    = (const float*)d_in[0];
    const float* Y    = (const float*)d_in[1];
    const float* W_xq = (const float*)d_in[2];
    const float* b_xq = (const float*)d_in[3];
    const float* W_yq = (const float*)d_in[4];
    const float* b_yq = (const float*)d_in[5];
    const float* W_fk = (const float*)d_in[6];
    const float* b_fk = (const float*)d_in[7];
    const float* W_fv = (const float*)d_in[8];
    const float* b_fv = (const float*)d_in[9];
    float* out = (float*)d_out;

#define SYM(T, name, gsym) T* name; cudaGetSymbolAddress((void**)&name, gsym)
    SYM(unsigned short, Xb, g_Xb);     SYM(unsigned short, Yb, g_Yb);
    SYM(unsigned short, Wxqb, g_Wxqb); SYM(unsigned short, Wyqb, g_Wyqb);
    SYM(unsigned short, Wfkb, g_Wfkb); SYM(unsigned short, Wfvb, g_Wfvb);
    SYM(unsigned short, Qb, g_Qb);     SYM(unsigned short, Kb, g_Kb);
    SYM(unsigned short, Vtb, g_Vtb);
    SYM(unsigned short, Pb1, g_Pb1);   SYM(unsigned short, Pb2, g_Pb2);
#undef SYM

    cudaFuncSetAttribute(hmma_tn, cudaFuncAttributeMaxDynamicSharedMemorySize, SMEM_TOTAL);

    const float scale = 0.04419417382415922f;  // 1/sqrt(512)
    const long long XBS = (long long)SS * DD;
    const long long QBS = (long long)SS * CC;
    const long long PBS = (long long)SS * SS;
    const long long VBS = (long long)DD * SS;

    // ---- bf16 conversions ----
    const int nX = NROW * DD;
    tobf16_dual<<<(2 * nX) / 256, 256>>>(X, Xb, Y, Yb, nX);
    tobf16_dual<<<(2 * DD * DD) / 256, 256>>>(W_xq, Wxqb, W_yq, Wyqb, DD * DD);
    tobf16_dual<<<(2 * DD * CC) / 256, 256>>>(W_fk, Wfkb, W_fv, Wfvb, DD * CC);

    // ---- projections: Q1 (z<8) and Q2 (z>=8) in one launch ----
    hmma_tn<<<dim3(4, 16, 16), 256, SMEM_TOTAL>>>(
        Xb, nullptr, DD, Wxqb, DD - 1,
        DD, DD, DD, XBS, 0, /*zsplit*/8,
        1, 1.f, b_xq, nullptr, Qb, QBS, CC, nullptr, nullptr,
        Yb, Wyqb, b_yq, Qb + DD, QBS, CC, 1);

    // ---- Kf (z<8, mode 1) and Vt (z>=8, mode 2 transposed) ----
    hmma_tn<<<dim3(4, 16, 16), 256, SMEM_TOTAL>>>(
        Qb, nullptr, CC, Wfkb, CC - 1,
        CC, CC, CC, QBS, 0, /*zsplit*/8,
        1, 1.f, b_fk, nullptr, Kb, XBS, DD, nullptr, nullptr,
        Qb, Wfvb, b_fv, Vtb, VBS, SS, 2);

    // ---- QK: scores for Q1 -> Pb1 (z<8) and Q2 -> Pb2 (z>=8) ----
    hmma_tn<<<dim3(16, 16, 16), 256, SMEM_TOTAL>>>(
        Qb, nullptr, DD, Kb, DD - 1,
        DD, CC, DD, QBS, XBS, /*zsplit*/8,
        5, scale, nullptr, nullptr, Pb1, PBS, SS, nullptr, nullptr,
        Qb + DD, Kb, nullptr, Pb2, PBS, SS, 5);

    // ---- softmax over both buffers ----
    softmax_bf16<<<2 * NROW, 256>>>(Pb1, Pb2);

    // ---- fused PV: out = P1@Vt^T + P2@Vt^T + X + Y  (K = 4096 concat) ----
    hmma_tn<<<dim3(4, 16, 8), 256, SMEM_TOTAL>>>(
        Pb1, Pb2, SS, Vtb, SS - 1,
        2 * SS, SS, SS, PBS, VBS, /*zsplit*/0,
        3, 1.f, nullptr, out, nullptr, XBS, DD, X, Y,
        nullptr, nullptr, nullptr, nullptr, 0, 0, 0);
}